// round 12
// baseline (speedup 1.0000x reference)
#include <cuda_runtime.h>
#include <cstdint>

#define NN 100000
#define NE 3200000

typedef unsigned long long ull;

// ---------------- device scratch ----------------
__device__ int2   g_edges[NE];      // (src, norm-as-float-bits), CSR by dst
__device__ int    g_src[NE];
__device__ int    g_dst[NE];
__device__ int    g_cnt[NN];
__device__ int    g_rowptr[NN + 1];
__device__ int    g_cursor[NN];
__device__ int    g_bsum[128];
__device__ int    g_bsumEx[128];
__device__ float  g_dinv[NN];
__device__ float4 g_bufA[NN * 4];   // xw  -> (reused) H
__device__ float4 g_bufC[NN * 4];   // xw2
__device__ float4 g_x1[NN * 4];
__device__ float4 g_x2[NN * 4];

// ---------------- helpers ----------------
__device__ __forceinline__ float sigm_f(float x) {
    return __fdividef(1.0f, 1.0f + __expf(-x));
}
__device__ __forceinline__ float tanh_f(float x) {
    float e = __expf(2.0f * x);
    return 1.0f - __fdividef(2.0f, e + 1.0f);
}
__device__ __forceinline__ ull pack2(float a, float b) {
    ull r;
    asm("mov.b64 %0, {%1, %2};" : "=l"(r) : "f"(a), "f"(b));
    return r;
}
__device__ __forceinline__ ull fma2(ull a, ull b, ull c) {
    ull d;
    asm("fma.rn.f32x2 %0, %1, %2, %3;" : "=l"(d) : "l"(a), "l"(b), "l"(c));
    return d;
}
__device__ __forceinline__ void unpack2(ull v, float& a, float& b) {
    asm("mov.b64 {%0, %1}, %2;" : "=f"(a), "=f"(b) : "l"(v));
}
#define FMA2W(acc, w, xv) (acc) = fma2(pack2((w), (w)), (xv), (acc))

#define CP16(dst, src) \
    asm volatile("cp.async.cg.shared.global [%0], [%1], 16;" :: "r"(dst), "l"(src))
#define CPCOMMIT() asm volatile("cp.async.commit_group;")
#define CPWAIT(n)  asm volatile("cp.async.wait_group %0;" :: "n"(n))

// ---------------- graph preprocessing (round-3 exact) ----------------
__global__ void k_zero() {
    int i = blockIdx.x * blockDim.x + threadIdx.x;
    if (i < NN) g_cnt[i] = 0;
}

__global__ void k_count(const int* __restrict__ ei, int is64) {
    int e = blockIdx.x * blockDim.x + threadIdx.x;
    if (e >= NE) return;
    int s, d;
    if (is64) {
        s = ei[2 * e];
        d = ei[2 * (NE + e)];
    } else {
        s = ei[e];
        d = ei[NE + e];
    }
    g_src[e] = s; g_dst[e] = d;
    atomicAdd(&g_cnt[d], 1);
}

__global__ void k_dinv() {
    int i = blockIdx.x * blockDim.x + threadIdx.x;
    if (i < NN) g_dinv[i] = rsqrtf((float)g_cnt[i] + 1.0f);
}

__global__ void k_scanA() {
    __shared__ int sh[1024];
    int i = blockIdx.x * 1024 + threadIdx.x;
    int v = (i < NN) ? g_cnt[i] : 0;
    sh[threadIdx.x] = v;
    __syncthreads();
    #pragma unroll
    for (int off = 1; off < 1024; off <<= 1) {
        int t = (threadIdx.x >= off) ? sh[threadIdx.x - off] : 0;
        __syncthreads();
        sh[threadIdx.x] += t;
        __syncthreads();
    }
    if (i < NN) g_rowptr[i] = sh[threadIdx.x] - v;
    if (threadIdx.x == 1023) g_bsum[blockIdx.x] = sh[1023];
}

__global__ void k_scanB(int nb) {
    __shared__ int sh[128];
    int t = threadIdx.x;
    int v = (t < nb) ? g_bsum[t] : 0;
    sh[t] = v;
    __syncthreads();
    #pragma unroll
    for (int off = 1; off < 128; off <<= 1) {
        int tv = (t >= off) ? sh[t - off] : 0;
        __syncthreads();
        sh[t] += tv;
        __syncthreads();
    }
    g_bsumEx[t] = sh[t] - v;
}

__global__ void k_scanC() {
    int i = blockIdx.x * blockDim.x + threadIdx.x;
    if (i < NN) {
        int r = g_rowptr[i] + g_bsumEx[i >> 10];
        g_rowptr[i] = r;
        g_cursor[i] = r;
    }
    if (i == 0) g_rowptr[NN] = NE;
}

__global__ void k_scatter() {
    int e = blockIdx.x * blockDim.x + threadIdx.x;
    if (e >= NE) return;
    int s = g_src[e], d = g_dst[e];
    int p = atomicAdd(&g_cursor[d], 1);
    g_edges[p] = make_int2(s, __float_as_int(g_dinv[s] * g_dinv[d]));
}

// ---------------- GEMM1: K16 tiles, double-buffered, 3 blocks/SM ----------------
// xw = x[100000,512] @ W1[512,16].  Block = 256 threads, 256 rows, 32 K-tiles.
// xs: 2 buffers x 256 rows x 20 floats (80B rows: 16B-aligned, conflict-free).
#define G1_STRIDE    20
#define G1_BUF_FLOATS 5120             // 256 * 20
#define G1_XS_BYTES  40960             // 2 * 256 * 20 * 4
#define SMEM_G1      (G1_XS_BYTES + 32768)

__global__ void __launch_bounds__(256, 3) k_gemm1(const float4* __restrict__ x4,
                                                  const float* __restrict__ w) {
    extern __shared__ char g1sm[];
    float*      xs  = (float*)g1sm;
    ulonglong2* sws = (ulonglong2*)(g1sm + G1_XS_BYTES);

    int tid = threadIdx.x;
    int c4  = tid & 3;         // fixed float4-column within a K16 tile
    int r0  = tid >> 2;        // row base (0..63)

    // full W1 resident (2048 ulonglong2 = 32KB), coalesced
    const ulonglong2* w16 = (const ulonglong2*)w;
    #pragma unroll
    for (int i = 0; i < 8; i++) sws[i * 256 + tid] = w16[i * 256 + tid];

    // per-thread global src pointers for its 4 rows (clamped for tail block)
    const float4* src[4];
    #pragma unroll
    for (int j = 0; j < 4; j++) {
        int gr = blockIdx.x * 256 + j * 64 + r0;
        if (gr >= NN) gr = NN - 1;
        src[j] = x4 + gr * 128 + c4;
    }
    unsigned int xs_u = (unsigned int)__cvta_generic_to_shared(xs);
    unsigned int dst0 = xs_u + (unsigned int)(r0 * (G1_STRIDE * 4) + c4 * 16);
    const unsigned int rowstep = 64 * (G1_STRIDE * 4);
    const unsigned int bufstep = G1_BUF_FLOATS * 4;

    // prologue: tiles 0 and 1 in flight
    #pragma unroll
    for (int j = 0; j < 4; j++) CP16(dst0 + j * rowstep, src[j] + 0 * 4);
    CPCOMMIT();
    #pragma unroll
    for (int j = 0; j < 4; j++) CP16(dst0 + bufstep + j * rowstep, src[j] + 1 * 4);
    CPCOMMIT();

    ull acc2[8];
    #pragma unroll
    for (int p = 0; p < 8; p++) acc2[p] = 0ULL;

    #pragma unroll 1
    for (int kc = 0; kc < 32; kc++) {
        if (kc < 31) { CPWAIT(1); } else { CPWAIT(0); }
        __syncthreads();

        const float* xb = xs + (kc & 1) * G1_BUF_FLOATS + tid * G1_STRIDE;
        #pragma unroll
        for (int q = 0; q < 4; q++) {
            float4 xv = *(const float4*)(xb + q * 4);
            const ulonglong2* wp = sws + (kc * 16 + q * 4) * 4;
            {
                ull xd = pack2(xv.x, xv.x);
                ulonglong2 a = wp[0], b = wp[1], c = wp[2], d = wp[3];
                acc2[0] = fma2(a.x, xd, acc2[0]); acc2[1] = fma2(a.y, xd, acc2[1]);
                acc2[2] = fma2(b.x, xd, acc2[2]); acc2[3] = fma2(b.y, xd, acc2[3]);
                acc2[4] = fma2(c.x, xd, acc2[4]); acc2[5] = fma2(c.y, xd, acc2[5]);
                acc2[6] = fma2(d.x, xd, acc2[6]); acc2[7] = fma2(d.y, xd, acc2[7]);
            }
            {
                ull xd = pack2(xv.y, xv.y);
                ulonglong2 a = wp[4], b = wp[5], c = wp[6], d = wp[7];
                acc2[0] = fma2(a.x, xd, acc2[0]); acc2[1] = fma2(a.y, xd, acc2[1]);
                acc2[2] = fma2(b.x, xd, acc2[2]); acc2[3] = fma2(b.y, xd, acc2[3]);
                acc2[4] = fma2(c.x, xd, acc2[4]); acc2[5] = fma2(c.y, xd, acc2[5]);
                acc2[6] = fma2(d.x, xd, acc2[6]); acc2[7] = fma2(d.y, xd, acc2[7]);
            }
            {
                ull xd = pack2(xv.z, xv.z);
                ulonglong2 a = wp[8], b = wp[9], c = wp[10], d = wp[11];
                acc2[0] = fma2(a.x, xd, acc2[0]); acc2[1] = fma2(a.y, xd, acc2[1]);
                acc2[2] = fma2(b.x, xd, acc2[2]); acc2[3] = fma2(b.y, xd, acc2[3]);
                acc2[4] = fma2(c.x, xd, acc2[4]); acc2[5] = fma2(c.y, xd, acc2[5]);
                acc2[6] = fma2(d.x, xd, acc2[6]); acc2[7] = fma2(d.y, xd, acc2[7]);
            }
            {
                ull xd = pack2(xv.w, xv.w);
                ulonglong2 a = wp[12], b = wp[13], c = wp[14], d = wp[15];
                acc2[0] = fma2(a.x, xd, acc2[0]); acc2[1] = fma2(a.y, xd, acc2[1]);
                acc2[2] = fma2(b.x, xd, acc2[2]); acc2[3] = fma2(b.y, xd, acc2[3]);
                acc2[4] = fma2(c.x, xd, acc2[4]); acc2[5] = fma2(c.y, xd, acc2[5]);
                acc2[6] = fma2(d.x, xd, acc2[6]); acc2[7] = fma2(d.y, xd, acc2[7]);
            }
        }
        __syncthreads();
        if (kc < 30) {
            unsigned int db = dst0 + (kc & 1) * bufstep;
            #pragma unroll
            for (int j = 0; j < 4; j++) CP16(db + j * rowstep, src[j] + (kc + 2) * 4);
            CPCOMMIT();
        }
    }

    int row = blockIdx.x * 256 + tid;
    if (row < NN) {
        float o[16];
        #pragma unroll
        for (int p = 0; p < 8; p++) unpack2(acc2[p], o[2 * p], o[2 * p + 1]);
        g_bufA[row * 4 + 0] = make_float4(o[0],  o[1],  o[2],  o[3]);
        g_bufA[row * 4 + 1] = make_float4(o[4],  o[5],  o[6],  o[7]);
        g_bufA[row * 4 + 2] = make_float4(o[8],  o[9],  o[10], o[11]);
        g_bufA[row * 4 + 3] = make_float4(o[12], o[13], o[14], o[15]);
    }
}

// ---------------- GCN aggregation: warp-per-node, 4 lanes per edge --------------
template <int MODE>
__global__ void __launch_bounds__(256) k_agg(float* __restrict__ outp,
                                             const float* __restrict__ bias,
                                             const float4* __restrict__ W4,
                                             const float* __restrict__ Wb) {
    __shared__ float4 sW[160];
    __shared__ float  sx[8][16];
    if (MODE == 0) { if (threadIdx.x < 64)  sW[threadIdx.x] = W4[threadIdx.x]; }
    if (MODE == 2) { if (threadIdx.x < 160) sW[threadIdx.x] = W4[threadIdx.x]; }
    __syncthreads();

    int warp = threadIdx.x >> 5;
    int lane = threadIdx.x & 31;
    int g = lane >> 2, q = lane & 3;
    int n = blockIdx.x * 8 + warp;
    if (n >= NN) return;

    const float4* in4 = (MODE == 1) ? g_bufC : g_bufA;

    float4 acc = make_float4(0.f, 0.f, 0.f, 0.f);
    if (g == 0) {
        float dd = g_dinv[n]; dd *= dd;
        float4 a = in4[n * 4 + q];
        acc.x = dd * a.x; acc.y = dd * a.y; acc.z = dd * a.z; acc.w = dd * a.w;
    }

    int beg = g_rowptr[n], end = g_rowptr[n + 1];
    for (int e = beg + g; e < end; e += 8) {
        int2 ev = g_edges[e];
        float w = __int_as_float(ev.y);
        float4 v = in4[ev.x * 4 + q];
        acc.x += w * v.x; acc.y += w * v.y; acc.z += w * v.z; acc.w += w * v.w;
    }

    #pragma unroll
    for (int off = 4; off < 32; off <<= 1) {
        acc.x += __shfl_xor_sync(0xffffffffu, acc.x, off);
        acc.y += __shfl_xor_sync(0xffffffffu, acc.y, off);
        acc.z += __shfl_xor_sync(0xffffffffu, acc.z, off);
        acc.w += __shfl_xor_sync(0xffffffffu, acc.w, off);
    }

    if (MODE == 0 || MODE == 1) {
        if (g == 0) {
            float4 b = ((const float4*)bias)[q];
            float4 xr;
            xr.x = fmaxf(acc.x + b.x, 0.0f);
            xr.y = fmaxf(acc.y + b.y, 0.0f);
            xr.z = fmaxf(acc.z + b.z, 0.0f);
            xr.w = fmaxf(acc.w + b.w, 0.0f);
            float4* ox = (MODE == 0) ? (g_x1 + n * 4) : (g_x2 + n * 4);
            ox[q] = xr;
            if (MODE == 0) {
                sx[warp][q * 4 + 0] = xr.x; sx[warp][q * 4 + 1] = xr.y;
                sx[warp][q * 4 + 2] = xr.z; sx[warp][q * 4 + 3] = xr.w;
            }
        }
        if (MODE == 0) {
            __syncwarp();
            if (g == 0) {
                float y[4] = {0.f, 0.f, 0.f, 0.f};
                #pragma unroll
                for (int k = 0; k < 16; k++) {
                    float xv = sx[warp][k];
                    float4 w = sW[k * 4 + q];
                    y[0] += xv * w.x; y[1] += xv * w.y;
                    y[2] += xv * w.z; y[3] += xv * w.w;
                }
                g_bufC[n * 4 + q] = make_float4(y[0], y[1], y[2], y[3]);
            }
        }
    } else {  // MODE 2
        if (g == 0) {
            sx[warp][q * 4 + 0] = acc.x; sx[warp][q * 4 + 1] = acc.y;
            sx[warp][q * 4 + 2] = acc.z; sx[warp][q * 4 + 3] = acc.w;
        }
        __syncwarp();
        const float* sWf = (const float*)sW;
        float v0 = __ldg(&Wb[lane]);
        float v1 = (lane < 8) ? __ldg(&Wb[32 + lane]) : -1e30f;
        #pragma unroll
        for (int k = 0; k < 16; k++) {
            float a = sx[warp][k];
            v0 += a * sWf[k * 40 + lane];
            if (lane < 8) v1 += a * sWf[k * 40 + 32 + lane];
        }
        float m = fmaxf(v0, v1);
        #pragma unroll
        for (int off = 1; off < 32; off <<= 1)
            m = fmaxf(m, __shfl_xor_sync(0xffffffffu, m, off));
        float s = __expf(v0 - m) + ((lane < 8) ? __expf(v1 - m) : 0.0f);
        #pragma unroll
        for (int off = 1; off < 32; off <<= 1)
            s += __shfl_xor_sync(0xffffffffu, s, off);
        float lse = m + __logf(s);
        outp[n * 40 + lane] = v0 - lse;
        if (lane < 8) outp[n * 40 + 32 + lane] = v1 - lse;
    }
}

// ---------------- JK bidirectional LSTM (round-3 exact: 401.5us config) ---------
#define LS_SIHF 0        // float4[512]   8KB  w_ih_f
#define LS_SIHB 8192     // float4[512]   8KB  w_ih_b
#define LS_SHH  16384    // float4[1024] 16KB  w_hh (fwd, then bwd)
#define LS_BF   32768    // float[128]
#define LS_BB   33280    // float[128]
#define LS_AW   33792    // float[64]
#define LS_H    34048    // ull[32*128]  32KB
#define LS_C    66816    // ull[32*128]  32KB
#define SMEM_LSTM 99584

__device__ __forceinline__ void cell0p(const ull* __restrict__ xp,
                                       ull* __restrict__ hsh, ull* __restrict__ csh,
                                       const float4* __restrict__ sih,
                                       const float* __restrict__ sb,
                                       const float* __restrict__ sw, ull& sacc) {
    #pragma unroll 1
    for (int j = 0; j < 32; j++) {
        float bi = sb[j], bg = sb[64 + j], bo = sb[96 + j];
        ull ai = pack2(bi, bi), ag = pack2(bg, bg), ao = pack2(bo, bo);
        #pragma unroll
        for (int q = 0; q < 4; q++) {
            float4 wi = sih[j * 4 + q];
            FMA2W(ai, wi.x, xp[4 * q + 0]); FMA2W(ai, wi.y, xp[4 * q + 1]);
            FMA2W(ai, wi.z, xp[4 * q + 2]); FMA2W(ai, wi.w, xp[4 * q + 3]);
            float4 wg = sih[(64 + j) * 4 + q];
            FMA2W(ag, wg.x, xp[4 * q + 0]); FMA2W(ag, wg.y, xp[4 * q + 1]);
            FMA2W(ag, wg.z, xp[4 * q + 2]); FMA2W(ag, wg.w, xp[4 * q + 3]);
            float4 wo = sih[(96 + j) * 4 + q];
            FMA2W(ao, wo.x, xp[4 * q + 0]); FMA2W(ao, wo.y, xp[4 * q + 1]);
            FMA2W(ao, wo.z, xp[4 * q + 2]); FMA2W(ao, wo.w, xp[4 * q + 3]);
        }
        float i0, i1, g0, g1, o0, o1;
        unpack2(ai, i0, i1); unpack2(ag, g0, g1); unpack2(ao, o0, o1);
        float c0 = sigm_f(i0) * tanh_f(g0), c1 = sigm_f(i1) * tanh_f(g1);
        float h0 = sigm_f(o0) * tanh_f(c0), h1 = sigm_f(o1) * tanh_f(c1);
        csh[j * 128] = pack2(c0, c1);
        ull hp = pack2(h0, h1);
        hsh[j * 128] = hp;
        float awj = sw[j];
        sacc = fma2(hp, pack2(awj, awj), sacc);
    }
}

__device__ __forceinline__ void cell1p(const ull* __restrict__ xp,
                                       const ull* __restrict__ hreg,
                                       const ull* __restrict__ csh,
                                       const float4* __restrict__ sih,
                                       const float4* __restrict__ shh,
                                       const float* __restrict__ sb,
                                       const float* __restrict__ sw, ull& sacc) {
    #pragma unroll 1
    for (int j = 0; j < 32; j++) {
        float bi = sb[j], bff = sb[32 + j], bg = sb[64 + j], bo = sb[96 + j];
        ull ai = pack2(bi, bi), af = pack2(bff, bff);
        ull ag = pack2(bg, bg), ao = pack2(bo, bo);
        #pragma unroll
        for (int q = 0; q < 4; q++) {
            float4 wi = sih[j * 4 + q];
            FMA2W(ai, wi.x, xp[4 * q + 0]); FMA2W(ai, wi.y, xp[4 * q + 1]);
            FMA2W(ai, wi.z, xp[4 * q + 2]); FMA2W(ai, wi.w, xp[4 * q + 3]);
            float4 wf = sih[(32 + j) * 4 + q];
            FMA2W(af, wf.x, xp[4 * q + 0]); FMA2W(af, wf.y, xp[4 * q + 1]);
            FMA2W(af, wf.z, xp[4 * q + 2]); FMA2W(af, wf.w, xp[4 * q + 3]);
            float4 wg = sih[(64 + j) * 4 + q];
            FMA2W(ag, wg.x, xp[4 * q + 0]); FMA2W(ag, wg.y, xp[4 * q + 1]);
            FMA2W(ag, wg.z, xp[4 * q + 2]); FMA2W(ag, wg.w, xp[4 * q + 3]);
            float4 wo = sih[(96 + j) * 4 + q];
            FMA2W(ao, wo.x, xp[4 * q + 0]); FMA2W(ao, wo.y, xp[4 * q + 1]);
            FMA2W(ao, wo.z, xp[4 * q + 2]); FMA2W(ao, wo.w, xp[4 * q + 3]);
        }
        #pragma unroll
        for (int q = 0; q < 8; q++) {
            float4 wi = shh[j * 8 + q];
            FMA2W(ai, wi.x, hreg[4 * q + 0]); FMA2W(ai, wi.y, hreg[4 * q + 1]);
            FMA2W(ai, wi.z, hreg[4 * q + 2]); FMA2W(ai, wi.w, hreg[4 * q + 3]);
            float4 wf = shh[(32 + j) * 8 + q];
            FMA2W(af, wf.x, hreg[4 * q + 0]); FMA2W(af, wf.y, hreg[4 * q + 1]);
            FMA2W(af, wf.z, hreg[4 * q + 2]); FMA2W(af, wf.w, hreg[4 * q + 3]);
            float4 wg = shh[(64 + j) * 8 + q];
            FMA2W(ag, wg.x, hreg[4 * q + 0]); FMA2W(ag, wg.y, hreg[4 * q + 1]);
            FMA2W(ag, wg.z, hreg[4 * q + 2]); FMA2W(ag, wg.w, hreg[4 * q + 3]);
            float4 wo = shh[(96 + j) * 8 + q];
            FMA2W(ao, wo.x, hreg[4 * q + 0]); FMA2W(ao, wo.y, hreg[4 * q + 1]);
            FMA2W(ao, wo.z, hreg[4 * q + 2]); FMA2W(ao, wo.w, hreg[4 * q + 3]);
        }
        float i0, i1, f0, f1, g0, g1, o0, o1;
        unpack2(ai, i0, i1); unpack2(af, f0, f1);
        unpack2(ag, g0, g1); unpack2(ao, o0, o1);
        float cp0, cp1;
        unpack2(csh[j * 128], cp0, cp1);
        float c0 = sigm_f(f0) * cp0 + sigm_f(i0) * tanh_f(g0);
        float c1 = sigm_f(f1) * cp1 + sigm_f(i1) * tanh_f(g1);
        float h0 = sigm_f(o0) * tanh_f(c0), h1 = sigm_f(o1) * tanh_f(c1);
        float awj = sw[j];
        sacc = fma2(pack2(h0, h1), pack2(awj, awj), sacc);
    }
}

__global__ void __launch_bounds__(128, 2) k_lstm(
    const float4* __restrict__ wihf, const float4* __restrict__ whhf, const float* __restrict__ bf,
    const float4* __restrict__ wihb, const float4* __restrict__ whhb, const float* __restrict__ bb,
    const float* __restrict__ aw, const float* __restrict__ ab) {
    extern __shared__ char sm[];
    float4* sihf = (float4*)(sm + LS_SIHF);
    float4* sihb = (float4*)(sm + LS_SIHB);
    float4* shh  = (float4*)(sm + LS_SHH);
    float*  sbf  = (float*)(sm + LS_BF);
    float*  sbb  = (float*)(sm + LS_BB);
    float*  saw  = (float*)(sm + LS_AW);
    int tid = threadIdx.x;
    ull* hsh = (ull*)(sm + LS_H) + tid;
    ull* csh = (ull*)(sm + LS_C) + tid;

    for (int i = tid; i < 512; i += 128) { sihf[i] = wihf[i]; sihb[i] = wihb[i]; }
    for (int i = tid; i < 1024; i += 128) shh[i] = whhf[i];
    if (tid < 64) {
        sbf[tid] = bf[tid]; sbf[64 + tid] = bf[64 + tid];
        sbb[tid] = bb[tid]; sbb[64 + tid] = bb[64 + tid];
        saw[tid] = aw[tid];
    }
    __syncthreads();

    int n0 = blockIdx.x * 256 + tid;
    int n1 = n0 + 128;
    bool v0 = n0 < NN, v1 = n1 < NN;
    int m0 = v0 ? n0 : 0, m1 = v1 ? n1 : 0;

    ull xpa[16], xpb[16];
    {
        #pragma unroll
        for (int q = 0; q < 4; q++) {
            float4 a = g_x1[m0 * 4 + q], b = g_x1[m1 * 4 + q];
            xpa[4 * q + 0] = pack2(a.x, b.x); xpa[4 * q + 1] = pack2(a.y, b.y);
            xpa[4 * q + 2] = pack2(a.z, b.z); xpa[4 * q + 3] = pack2(a.w, b.w);
            float4 c = g_x2[m0 * 4 + q], d = g_x2[m1 * 4 + q];
            xpb[4 * q + 0] = pack2(c.x, d.x); xpb[4 * q + 1] = pack2(c.y, d.y);
            xpb[4 * q + 2] = pack2(c.z, d.z); xpb[4 * q + 3] = pack2(c.w, d.w);
        }
    }

    ull s0 = 0ULL, s1 = 0ULL;
    ull hreg[32];

    cell0p(xpa, hsh, csh, sihf, sbf, saw, s0);
    #pragma unroll
    for (int k = 0; k < 32; k++) hreg[k] = hsh[k * 128];
    cell1p(xpb, hreg, csh, sihf, shh, sbf, saw, s1);

    __syncthreads();
    for (int i = tid; i < 1024; i += 128) shh[i] = whhb[i];
    __syncthreads();

    cell0p(xpb, hsh, csh, sihb, sbb, saw + 32, s1);
    #pragma unroll
    for (int k = 0; k < 32; k++) hreg[k] = hsh[k * 128];
    cell1p(xpa, hreg, csh, sihb, shh, sbb, saw + 32, s0);

    float abv = __ldg(ab);
    float s00, s01, s10, s11;
    unpack2(s0, s00, s01); unpack2(s1, s10, s11);
    s00 += abv; s01 += abv; s10 += abv; s11 += abv;

    float mA = fmaxf(s00, s10);
    float eA0 = __expf(s00 - mA), eA1 = __expf(s10 - mA);
    float invA = __fdividef(1.0f, eA0 + eA1);
    float A0 = eA0 * invA, B0 = eA1 * invA;

    float mB = fmaxf(s01, s11);
    float eB0 = __expf(s01 - mB), eB1 = __expf(s11 - mB);
    float invB = __fdividef(1.0f, eB0 + eB1);
    float A1 = eB0 * invB, B1 = eB1 * invB;

    float fa[16], fb[16], ga[16], gb[16];
    #pragma unroll
    for (int k = 0; k < 16; k++) {
        float lo, hi;
        unpack2(xpa[k], lo, hi); fa[k] = lo; ga[k] = hi;
        unpack2(xpb[k], lo, hi); fb[k] = lo; gb[k] = hi;
    }
    if (v0) {
        #pragma unroll
        for (int q = 0; q < 4; q++) {
            g_bufA[n0 * 4 + q] = make_float4(
                A0 * fa[4 * q + 0] + B0 * fb[4 * q + 0],
                A0 * fa[4 * q + 1] + B0 * fb[4 * q + 1],
                A0 * fa[4 * q + 2] + B0 * fb[4 * q + 2],
                A0 * fa[4 * q + 3] + B0 * fb[4 * q + 3]);
        }
    }
    if (v1) {
        #pragma unroll
        for (int q = 0; q < 4; q++) {
            g_bufA[n1 * 4 + q] = make_float4(
                A1 * ga[4 * q + 0] + B1 * gb[4 * q + 0],
                A1 * ga[4 * q + 1] + B1 * gb[4 * q + 1],
                A1 * ga[4 * q + 2] + B1 * gb[4 * q + 2],
                A1 * ga[4 * q + 3] + B1 * gb[4 * q + 3]);
        }
    }
}

// ---------------- launch ----------------
extern "C" void kernel_launch(void* const* d_in, const int* in_sizes, int n_in,
                              void* d_out, int out_size) {
    int is64 = (in_sizes[1] >= 4 * NE) ? 1 : 0;

    const int NB_N  = (NN + 255) / 256;
    const int NB_E  = (NE + 255) / 256;
    const int NB_SC = (NN + 1023) / 1024;
    const int NB_W  = (NN + 7) / 8;
    const int NB_L  = (NN + 255) / 256;

    cudaFuncSetAttribute(k_lstm, cudaFuncAttributeMaxDynamicSharedMemorySize, SMEM_LSTM);
    cudaFuncSetAttribute(k_gemm1, cudaFuncAttributeMaxDynamicSharedMemorySize, SMEM_G1);

    k_zero<<<NB_N, 256>>>();
    k_count<<<NB_E, 256>>>((const int*)d_in[1], is64);
    k_dinv<<<NB_N, 256>>>();
    k_gemm1<<<NB_N, 256, SMEM_G1>>>((const float4*)d_in[0], (const float*)d_in[2]);
    k_scanA<<<NB_SC, 1024>>>();
    k_scanB<<<1, 128>>>(NB_SC);
    k_scanC<<<NB_N, 256>>>();
    k_scatter<<<NB_E, 256>>>();

    k_agg<0><<<NB_W, 256>>>(nullptr, (const float*)d_in[3], (const float4*)d_in[4], nullptr);
    k_agg<1><<<NB_W, 256>>>(nullptr, (const float*)d_in[5], nullptr, nullptr);

    k_lstm<<<NB_L, 128, SMEM_LSTM>>>(
        (const float4*)d_in[6], (const float4*)d_in[7], (const float*)d_in[8],
        (const float4*)d_in[9], (const float4*)d_in[10], (const float*)d_in[11],
        (const float*)d_in[12], (const float*)d_in[13]);

    k_agg<2><<<NB_W, 256>>>((float*)d_out, nullptr, (const float4*)d_in[14],
                            (const float*)d_in[15]);
}

// round 13
// speedup vs baseline: 1.0031x; 1.0031x over previous
#include <cuda_runtime.h>
#include <cstdint>

#define NN 100000
#define NE 3200000

typedef unsigned long long ull;

// ---------------- device scratch ----------------
__device__ int2   g_edges[NE];      // (src, norm-as-float-bits), CSR by dst
__device__ int    g_src[NE];
__device__ int    g_dst[NE];
__device__ int    g_cnt[NN];
__device__ int    g_rowptr[NN + 1];
__device__ int    g_cursor[NN];
__device__ int    g_bsum[128];
__device__ int    g_bsumEx[128];
__device__ float  g_dinv[NN];
__device__ float4 g_bufA[NN * 4];   // xw  -> (reused) H
__device__ float4 g_bufC[NN * 4];   // xw2
__device__ float4 g_x1[NN * 4];
__device__ float4 g_x2[NN * 4];

// ---------------- helpers ----------------
__device__ __forceinline__ float sigm_f(float x) {
    return __fdividef(1.0f, 1.0f + __expf(-x));
}
__device__ __forceinline__ float tanh_f(float x) {
    float e = __expf(2.0f * x);
    return 1.0f - __fdividef(2.0f, e + 1.0f);
}
__device__ __forceinline__ ull pack2(float a, float b) {
    ull r;
    asm("mov.b64 %0, {%1, %2};" : "=l"(r) : "f"(a), "f"(b));
    return r;
}
__device__ __forceinline__ ull fma2(ull a, ull b, ull c) {
    ull d;
    asm("fma.rn.f32x2 %0, %1, %2, %3;" : "=l"(d) : "l"(a), "l"(b), "l"(c));
    return d;
}
__device__ __forceinline__ void unpack2(ull v, float& a, float& b) {
    asm("mov.b64 {%0, %1}, %2;" : "=f"(a), "=f"(b) : "l"(v));
}
#define FMA2W(acc, w, xv) (acc) = fma2(pack2((w), (w)), (xv), (acc))

#define CP16(dst, src) \
    asm volatile("cp.async.cg.shared.global [%0], [%1], 16;" :: "r"(dst), "l"(src))
#define CPCOMMIT() asm volatile("cp.async.commit_group;")
#define CPWAIT(n)  asm volatile("cp.async.wait_group %0;" :: "n"(n))

// ---------------- graph preprocessing (round-3 exact) ----------------
__global__ void k_zero() {
    int i = blockIdx.x * blockDim.x + threadIdx.x;
    if (i < NN) g_cnt[i] = 0;
}

__global__ void k_count(const int* __restrict__ ei, int is64) {
    int e = blockIdx.x * blockDim.x + threadIdx.x;
    if (e >= NE) return;
    int s, d;
    if (is64) {
        s = ei[2 * e];
        d = ei[2 * (NE + e)];
    } else {
        s = ei[e];
        d = ei[NE + e];
    }
    g_src[e] = s; g_dst[e] = d;
    atomicAdd(&g_cnt[d], 1);
}

__global__ void k_dinv() {
    int i = blockIdx.x * blockDim.x + threadIdx.x;
    if (i < NN) g_dinv[i] = rsqrtf((float)g_cnt[i] + 1.0f);
}

__global__ void k_scanA() {
    __shared__ int sh[1024];
    int i = blockIdx.x * 1024 + threadIdx.x;
    int v = (i < NN) ? g_cnt[i] : 0;
    sh[threadIdx.x] = v;
    __syncthreads();
    #pragma unroll
    for (int off = 1; off < 1024; off <<= 1) {
        int t = (threadIdx.x >= off) ? sh[threadIdx.x - off] : 0;
        __syncthreads();
        sh[threadIdx.x] += t;
        __syncthreads();
    }
    if (i < NN) g_rowptr[i] = sh[threadIdx.x] - v;
    if (threadIdx.x == 1023) g_bsum[blockIdx.x] = sh[1023];
}

__global__ void k_scanB(int nb) {
    __shared__ int sh[128];
    int t = threadIdx.x;
    int v = (t < nb) ? g_bsum[t] : 0;
    sh[t] = v;
    __syncthreads();
    #pragma unroll
    for (int off = 1; off < 128; off <<= 1) {
        int tv = (t >= off) ? sh[t - off] : 0;
        __syncthreads();
        sh[t] += tv;
        __syncthreads();
    }
    g_bsumEx[t] = sh[t] - v;
}

__global__ void k_scanC() {
    int i = blockIdx.x * blockDim.x + threadIdx.x;
    if (i < NN) {
        int r = g_rowptr[i] + g_bsumEx[i >> 10];
        g_rowptr[i] = r;
        g_cursor[i] = r;
    }
    if (i == 0) g_rowptr[NN] = NE;
}

__global__ void k_scatter() {
    int e = blockIdx.x * blockDim.x + threadIdx.x;
    if (e >= NE) return;
    int s = g_src[e], d = g_dst[e];
    int p = atomicAdd(&g_cursor[d], 1);
    g_edges[p] = make_int2(s, __float_as_int(g_dinv[s] * g_dinv[d]));
}

// ---------------- GEMM1: K16 tiles, 3-stage cp.async ring ----------------------
// xw = x[100000,512] @ W1[512,16].  Block = 256 threads, 256 rows, 32 K-tiles.
// xs: 3 buffers x 256 rows x 20 floats (80B rows: 16B-aligned, conflict-free).
// Each tile's load has TWO compute phases of latency cover.
#define G1_STRIDE     20
#define G1_BUF_FLOATS 5120             // 256 * 20
#define G1_XS_BYTES   61440            // 3 * 256 * 20 * 4
#define SMEM_G1       (G1_XS_BYTES + 32768)

__global__ void __launch_bounds__(256, 2) k_gemm1(const float4* __restrict__ x4,
                                                  const float* __restrict__ w) {
    extern __shared__ char g1sm[];
    float*      xs  = (float*)g1sm;
    ulonglong2* sws = (ulonglong2*)(g1sm + G1_XS_BYTES);

    int tid = threadIdx.x;
    int c4  = tid & 3;         // fixed float4-column within a K16 tile
    int r0  = tid >> 2;        // row base (0..63)

    // full W1 resident (2048 ulonglong2 = 32KB), coalesced
    const ulonglong2* w16 = (const ulonglong2*)w;
    #pragma unroll
    for (int i = 0; i < 8; i++) sws[i * 256 + tid] = w16[i * 256 + tid];

    // per-thread global src pointers for its 4 rows (clamped for tail block)
    const float4* src[4];
    #pragma unroll
    for (int j = 0; j < 4; j++) {
        int gr = blockIdx.x * 256 + j * 64 + r0;
        if (gr >= NN) gr = NN - 1;
        src[j] = x4 + gr * 128 + c4;
    }
    unsigned int xs_u = (unsigned int)__cvta_generic_to_shared(xs);
    unsigned int dst0 = xs_u + (unsigned int)(r0 * (G1_STRIDE * 4) + c4 * 16);
    const unsigned int rowstep = 64 * (G1_STRIDE * 4);
    const unsigned int bufstep = G1_BUF_FLOATS * 4;

    // prologue: tiles 0,1,2 in flight (3 groups)
    #pragma unroll
    for (int t = 0; t < 3; t++) {
        #pragma unroll
        for (int j = 0; j < 4; j++) CP16(dst0 + t * bufstep + j * rowstep, src[j] + t * 4);
        CPCOMMIT();
    }

    ull acc2[8];
    #pragma unroll
    for (int p = 0; p < 8; p++) acc2[p] = 0ULL;

    int buf = 0;
    #pragma unroll 1
    for (int kc = 0; kc < 32; kc++) {
        if (kc < 30)      { CPWAIT(2); }
        else if (kc == 30){ CPWAIT(1); }
        else              { CPWAIT(0); }
        __syncthreads();

        const float* xb = xs + buf * G1_BUF_FLOATS + tid * G1_STRIDE;
        #pragma unroll
        for (int q = 0; q < 4; q++) {
            float4 xv = *(const float4*)(xb + q * 4);
            const ulonglong2* wp = sws + (kc * 16 + q * 4) * 4;
            {
                ull xd = pack2(xv.x, xv.x);
                ulonglong2 a = wp[0], b = wp[1], c = wp[2], d = wp[3];
                acc2[0] = fma2(a.x, xd, acc2[0]); acc2[1] = fma2(a.y, xd, acc2[1]);
                acc2[2] = fma2(b.x, xd, acc2[2]); acc2[3] = fma2(b.y, xd, acc2[3]);
                acc2[4] = fma2(c.x, xd, acc2[4]); acc2[5] = fma2(c.y, xd, acc2[5]);
                acc2[6] = fma2(d.x, xd, acc2[6]); acc2[7] = fma2(d.y, xd, acc2[7]);
            }
            {
                ull xd = pack2(xv.y, xv.y);
                ulonglong2 a = wp[4], b = wp[5], c = wp[6], d = wp[7];
                acc2[0] = fma2(a.x, xd, acc2[0]); acc2[1] = fma2(a.y, xd, acc2[1]);
                acc2[2] = fma2(b.x, xd, acc2[2]); acc2[3] = fma2(b.y, xd, acc2[3]);
                acc2[4] = fma2(c.x, xd, acc2[4]); acc2[5] = fma2(c.y, xd, acc2[5]);
                acc2[6] = fma2(d.x, xd, acc2[6]); acc2[7] = fma2(d.y, xd, acc2[7]);
            }
            {
                ull xd = pack2(xv.z, xv.z);
                ulonglong2 a = wp[8], b = wp[9], c = wp[10], d = wp[11];
                acc2[0] = fma2(a.x, xd, acc2[0]); acc2[1] = fma2(a.y, xd, acc2[1]);
                acc2[2] = fma2(b.x, xd, acc2[2]); acc2[3] = fma2(b.y, xd, acc2[3]);
                acc2[4] = fma2(c.x, xd, acc2[4]); acc2[5] = fma2(c.y, xd, acc2[5]);
                acc2[6] = fma2(d.x, xd, acc2[6]); acc2[7] = fma2(d.y, xd, acc2[7]);
            }
            {
                ull xd = pack2(xv.w, xv.w);
                ulonglong2 a = wp[12], b = wp[13], c = wp[14], d = wp[15];
                acc2[0] = fma2(a.x, xd, acc2[0]); acc2[1] = fma2(a.y, xd, acc2[1]);
                acc2[2] = fma2(b.x, xd, acc2[2]); acc2[3] = fma2(b.y, xd, acc2[3]);
                acc2[4] = fma2(c.x, xd, acc2[4]); acc2[5] = fma2(c.y, xd, acc2[5]);
                acc2[6] = fma2(d.x, xd, acc2[6]); acc2[7] = fma2(d.y, xd, acc2[7]);
            }
        }
        __syncthreads();
        if (kc < 29) {
            unsigned int db = dst0 + buf * bufstep;   // just-freed buffer
            #pragma unroll
            for (int j = 0; j < 4; j++) CP16(db + j * rowstep, src[j] + (kc + 3) * 4);
            CPCOMMIT();
        }
        buf++;
        if (buf == 3) buf = 0;
    }

    int row = blockIdx.x * 256 + tid;
    if (row < NN) {
        float o[16];
        #pragma unroll
        for (int p = 0; p < 8; p++) unpack2(acc2[p], o[2 * p], o[2 * p + 1]);
        g_bufA[row * 4 + 0] = make_float4(o[0],  o[1],  o[2],  o[3]);
        g_bufA[row * 4 + 1] = make_float4(o[4],  o[5],  o[6],  o[7]);
        g_bufA[row * 4 + 2] = make_float4(o[8],  o[9],  o[10], o[11]);
        g_bufA[row * 4 + 3] = make_float4(o[12], o[13], o[14], o[15]);
    }
}

// ---------------- GCN aggregation: warp-per-node, 4 lanes per edge --------------
template <int MODE>
__global__ void __launch_bounds__(256) k_agg(float* __restrict__ outp,
                                             const float* __restrict__ bias,
                                             const float4* __restrict__ W4,
                                             const float* __restrict__ Wb) {
    __shared__ float4 sW[160];
    __shared__ float  sx[8][16];
    if (MODE == 0) { if (threadIdx.x < 64)  sW[threadIdx.x] = W4[threadIdx.x]; }
    if (MODE == 2) { if (threadIdx.x < 160) sW[threadIdx.x] = W4[threadIdx.x]; }
    __syncthreads();

    int warp = threadIdx.x >> 5;
    int lane = threadIdx.x & 31;
    int g = lane >> 2, q = lane & 3;
    int n = blockIdx.x * 8 + warp;
    if (n >= NN) return;

    const float4* in4 = (MODE == 1) ? g_bufC : g_bufA;

    float4 acc = make_float4(0.f, 0.f, 0.f, 0.f);
    if (g == 0) {
        float dd = g_dinv[n]; dd *= dd;
        float4 a = in4[n * 4 + q];
        acc.x = dd * a.x; acc.y = dd * a.y; acc.z = dd * a.z; acc.w = dd * a.w;
    }

    int beg = g_rowptr[n], end = g_rowptr[n + 1];
    for (int e = beg + g; e < end; e += 8) {
        int2 ev = g_edges[e];
        float w = __int_as_float(ev.y);
        float4 v = in4[ev.x * 4 + q];
        acc.x += w * v.x; acc.y += w * v.y; acc.z += w * v.z; acc.w += w * v.w;
    }

    #pragma unroll
    for (int off = 4; off < 32; off <<= 1) {
        acc.x += __shfl_xor_sync(0xffffffffu, acc.x, off);
        acc.y += __shfl_xor_sync(0xffffffffu, acc.y, off);
        acc.z += __shfl_xor_sync(0xffffffffu, acc.z, off);
        acc.w += __shfl_xor_sync(0xffffffffu, acc.w, off);
    }

    if (MODE == 0 || MODE == 1) {
        if (g == 0) {
            float4 b = ((const float4*)bias)[q];
            float4 xr;
            xr.x = fmaxf(acc.x + b.x, 0.0f);
            xr.y = fmaxf(acc.y + b.y, 0.0f);
            xr.z = fmaxf(acc.z + b.z, 0.0f);
            xr.w = fmaxf(acc.w + b.w, 0.0f);
            float4* ox = (MODE == 0) ? (g_x1 + n * 4) : (g_x2 + n * 4);
            ox[q] = xr;
            if (MODE == 0) {
                sx[warp][q * 4 + 0] = xr.x; sx[warp][q * 4 + 1] = xr.y;
                sx[warp][q * 4 + 2] = xr.z; sx[warp][q * 4 + 3] = xr.w;
            }
        }
        if (MODE == 0) {
            __syncwarp();
            if (g == 0) {
                float y[4] = {0.f, 0.f, 0.f, 0.f};
                #pragma unroll
                for (int k = 0; k < 16; k++) {
                    float xv = sx[warp][k];
                    float4 w = sW[k * 4 + q];
                    y[0] += xv * w.x; y[1] += xv * w.y;
                    y[2] += xv * w.z; y[3] += xv * w.w;
                }
                g_bufC[n * 4 + q] = make_float4(y[0], y[1], y[2], y[3]);
            }
        }
    } else {  // MODE 2
        if (g == 0) {
            sx[warp][q * 4 + 0] = acc.x; sx[warp][q * 4 + 1] = acc.y;
            sx[warp][q * 4 + 2] = acc.z; sx[warp][q * 4 + 3] = acc.w;
        }
        __syncwarp();
        const float* sWf = (const float*)sW;
        float v0 = __ldg(&Wb[lane]);
        float v1 = (lane < 8) ? __ldg(&Wb[32 + lane]) : -1e30f;
        #pragma unroll
        for (int k = 0; k < 16; k++) {
            float a = sx[warp][k];
            v0 += a * sWf[k * 40 + lane];
            if (lane < 8) v1 += a * sWf[k * 40 + 32 + lane];
        }
        float m = fmaxf(v0, v1);
        #pragma unroll
        for (int off = 1; off < 32; off <<= 1)
            m = fmaxf(m, __shfl_xor_sync(0xffffffffu, m, off));
        float s = __expf(v0 - m) + ((lane < 8) ? __expf(v1 - m) : 0.0f);
        #pragma unroll
        for (int off = 1; off < 32; off <<= 1)
            s += __shfl_xor_sync(0xffffffffu, s, off);
        float lse = m + __logf(s);
        outp[n * 40 + lane] = v0 - lse;
        if (lane < 8) outp[n * 40 + 32 + lane] = v1 - lse;
    }
}

// ---------------- JK bidirectional LSTM (round-3 exact: 401.5us config) ---------
#define LS_SIHF 0        // float4[512]   8KB  w_ih_f
#define LS_SIHB 8192     // float4[512]   8KB  w_ih_b
#define LS_SHH  16384    // float4[1024] 16KB  w_hh (fwd, then bwd)
#define LS_BF   32768    // float[128]
#define LS_BB   33280    // float[128]
#define LS_AW   33792    // float[64]
#define LS_H    34048    // ull[32*128]  32KB
#define LS_C    66816    // ull[32*128]  32KB
#define SMEM_LSTM 99584

__device__ __forceinline__ void cell0p(const ull* __restrict__ xp,
                                       ull* __restrict__ hsh, ull* __restrict__ csh,
                                       const float4* __restrict__ sih,
                                       const float* __restrict__ sb,
                                       const float* __restrict__ sw, ull& sacc) {
    #pragma unroll 1
    for (int j = 0; j < 32; j++) {
        float bi = sb[j], bg = sb[64 + j], bo = sb[96 + j];
        ull ai = pack2(bi, bi), ag = pack2(bg, bg), ao = pack2(bo, bo);
        #pragma unroll
        for (int q = 0; q < 4; q++) {
            float4 wi = sih[j * 4 + q];
            FMA2W(ai, wi.x, xp[4 * q + 0]); FMA2W(ai, wi.y, xp[4 * q + 1]);
            FMA2W(ai, wi.z, xp[4 * q + 2]); FMA2W(ai, wi.w, xp[4 * q + 3]);
            float4 wg = sih[(64 + j) * 4 + q];
            FMA2W(ag, wg.x, xp[4 * q + 0]); FMA2W(ag, wg.y, xp[4 * q + 1]);
            FMA2W(ag, wg.z, xp[4 * q + 2]); FMA2W(ag, wg.w, xp[4 * q + 3]);
            float4 wo = sih[(96 + j) * 4 + q];
            FMA2W(ao, wo.x, xp[4 * q + 0]); FMA2W(ao, wo.y, xp[4 * q + 1]);
            FMA2W(ao, wo.z, xp[4 * q + 2]); FMA2W(ao, wo.w, xp[4 * q + 3]);
        }
        float i0, i1, g0, g1, o0, o1;
        unpack2(ai, i0, i1); unpack2(ag, g0, g1); unpack2(ao, o0, o1);
        float c0 = sigm_f(i0) * tanh_f(g0), c1 = sigm_f(i1) * tanh_f(g1);
        float h0 = sigm_f(o0) * tanh_f(c0), h1 = sigm_f(o1) * tanh_f(c1);
        csh[j * 128] = pack2(c0, c1);
        ull hp = pack2(h0, h1);
        hsh[j * 128] = hp;
        float awj = sw[j];
        sacc = fma2(hp, pack2(awj, awj), sacc);
    }
}

__device__ __forceinline__ void cell1p(const ull* __restrict__ xp,
                                       const ull* __restrict__ hreg,
                                       const ull* __restrict__ csh,
                                       const float4* __restrict__ sih,
                                       const float4* __restrict__ shh,
                                       const float* __restrict__ sb,
                                       const float* __restrict__ sw, ull& sacc) {
    #pragma unroll 1
    for (int j = 0; j < 32; j++) {
        float bi = sb[j], bff = sb[32 + j], bg = sb[64 + j], bo = sb[96 + j];
        ull ai = pack2(bi, bi), af = pack2(bff, bff);
        ull ag = pack2(bg, bg), ao = pack2(bo, bo);
        #pragma unroll
        for (int q = 0; q < 4; q++) {
            float4 wi = sih[j * 4 + q];
            FMA2W(ai, wi.x, xp[4 * q + 0]); FMA2W(ai, wi.y, xp[4 * q + 1]);
            FMA2W(ai, wi.z, xp[4 * q + 2]); FMA2W(ai, wi.w, xp[4 * q + 3]);
            float4 wf = sih[(32 + j) * 4 + q];
            FMA2W(af, wf.x, xp[4 * q + 0]); FMA2W(af, wf.y, xp[4 * q + 1]);
            FMA2W(af, wf.z, xp[4 * q + 2]); FMA2W(af, wf.w, xp[4 * q + 3]);
            float4 wg = sih[(64 + j) * 4 + q];
            FMA2W(ag, wg.x, xp[4 * q + 0]); FMA2W(ag, wg.y, xp[4 * q + 1]);
            FMA2W(ag, wg.z, xp[4 * q + 2]); FMA2W(ag, wg.w, xp[4 * q + 3]);
            float4 wo = sih[(96 + j) * 4 + q];
            FMA2W(ao, wo.x, xp[4 * q + 0]); FMA2W(ao, wo.y, xp[4 * q + 1]);
            FMA2W(ao, wo.z, xp[4 * q + 2]); FMA2W(ao, wo.w, xp[4 * q + 3]);
        }
        #pragma unroll
        for (int q = 0; q < 8; q++) {
            float4 wi = shh[j * 8 + q];
            FMA2W(ai, wi.x, hreg[4 * q + 0]); FMA2W(ai, wi.y, hreg[4 * q + 1]);
            FMA2W(ai, wi.z, hreg[4 * q + 2]); FMA2W(ai, wi.w, hreg[4 * q + 3]);
            float4 wf = shh[(32 + j) * 8 + q];
            FMA2W(af, wf.x, hreg[4 * q + 0]); FMA2W(af, wf.y, hreg[4 * q + 1]);
            FMA2W(af, wf.z, hreg[4 * q + 2]); FMA2W(af, wf.w, hreg[4 * q + 3]);
            float4 wg = shh[(64 + j) * 8 + q];
            FMA2W(ag, wg.x, hreg[4 * q + 0]); FMA2W(ag, wg.y, hreg[4 * q + 1]);
            FMA2W(ag, wg.z, hreg[4 * q + 2]); FMA2W(ag, wg.w, hreg[4 * q + 3]);
            float4 wo = shh[(96 + j) * 8 + q];
            FMA2W(ao, wo.x, hreg[4 * q + 0]); FMA2W(ao, wo.y, hreg[4 * q + 1]);
            FMA2W(ao, wo.z, hreg[4 * q + 2]); FMA2W(ao, wo.w, hreg[4 * q + 3]);
        }
        float i0, i1, f0, f1, g0, g1, o0, o1;
        unpack2(ai, i0, i1); unpack2(af, f0, f1);
        unpack2(ag, g0, g1); unpack2(ao, o0, o1);
        float cp0, cp1;
        unpack2(csh[j * 128], cp0, cp1);
        float c0 = sigm_f(f0) * cp0 + sigm_f(i0) * tanh_f(g0);
        float c1 = sigm_f(f1) * cp1 + sigm_f(i1) * tanh_f(g1);
        float h0 = sigm_f(o0) * tanh_f(c0), h1 = sigm_f(o1) * tanh_f(c1);
        float awj = sw[j];
        sacc = fma2(pack2(h0, h1), pack2(awj, awj), sacc);
    }
}

__global__ void __launch_bounds__(128, 2) k_lstm(
    const float4* __restrict__ wihf, const float4* __restrict__ whhf, const float* __restrict__ bf,
    const float4* __restrict__ wihb, const float4* __restrict__ whhb, const float* __restrict__ bb,
    const float* __restrict__ aw, const float* __restrict__ ab) {
    extern __shared__ char sm[];
    float4* sihf = (float4*)(sm + LS_SIHF);
    float4* sihb = (float4*)(sm + LS_SIHB);
    float4* shh  = (float4*)(sm + LS_SHH);
    float*  sbf  = (float*)(sm + LS_BF);
    float*  sbb  = (float*)(sm + LS_BB);
    float*  saw  = (float*)(sm + LS_AW);
    int tid = threadIdx.x;
    ull* hsh = (ull*)(sm + LS_H) + tid;
    ull* csh = (ull*)(sm + LS_C) + tid;

    for (int i = tid; i < 512; i += 128) { sihf[i] = wihf[i]; sihb[i] = wihb[i]; }
    for (int i = tid; i < 1024; i += 128) shh[i] = whhf[i];
    if (tid < 64) {
        sbf[tid] = bf[tid]; sbf[64 + tid] = bf[64 + tid];
        sbb[tid] = bb[tid]; sbb[64 + tid] = bb[64 + tid];
        saw[tid] = aw[tid];
    }
    __syncthreads();

    int n0 = blockIdx.x * 256 + tid;
    int n1 = n0 + 128;
    bool v0 = n0 < NN, v1 = n1 < NN;
    int m0 = v0 ? n0 : 0, m1 = v1 ? n1 : 0;

    ull xpa[16], xpb[16];
    {
        #pragma unroll
        for (int q = 0; q < 4; q++) {
            float4 a = g_x1[m0 * 4 + q], b = g_x1[m1 * 4 + q];
            xpa[4 * q + 0] = pack2(a.x, b.x); xpa[4 * q + 1] = pack2(a.y, b.y);
            xpa[4 * q + 2] = pack2(a.z, b.z); xpa[4 * q + 3] = pack2(a.w, b.w);
            float4 c = g_x2[m0 * 4 + q], d = g_x2[m1 * 4 + q];
            xpb[4 * q + 0] = pack2(c.x, d.x); xpb[4 * q + 1] = pack2(c.y, d.y);
            xpb[4 * q + 2] = pack2(c.z, d.z); xpb[4 * q + 3] = pack2(c.w, d.w);
        }
    }

    ull s0 = 0ULL, s1 = 0ULL;
    ull hreg[32];

    cell0p(xpa, hsh, csh, sihf, sbf, saw, s0);
    #pragma unroll
    for (int k = 0; k < 32; k++) hreg[k] = hsh[k * 128];
    cell1p(xpb, hreg, csh, sihf, shh, sbf, saw, s1);

    __syncthreads();
    for (int i = tid; i < 1024; i += 128) shh[i] = whhb[i];
    __syncthreads();

    cell0p(xpb, hsh, csh, sihb, sbb, saw + 32, s1);
    #pragma unroll
    for (int k = 0; k < 32; k++) hreg[k] = hsh[k * 128];
    cell1p(xpa, hreg, csh, sihb, shh, sbb, saw + 32, s0);

    float abv = __ldg(ab);
    float s00, s01, s10, s11;
    unpack2(s0, s00, s01); unpack2(s1, s10, s11);
    s00 += abv; s01 += abv; s10 += abv; s11 += abv;

    float mA = fmaxf(s00, s10);
    float eA0 = __expf(s00 - mA), eA1 = __expf(s10 - mA);
    float invA = __fdividef(1.0f, eA0 + eA1);
    float A0 = eA0 * invA, B0 = eA1 * invA;

    float mB = fmaxf(s01, s11);
    float eB0 = __expf(s01 - mB), eB1 = __expf(s11 - mB);
    float invB = __fdividef(1.0f, eB0 + eB1);
    float A1 = eB0 * invB, B1 = eB1 * invB;

    float fa[16], fb[16], ga[16], gb[16];
    #pragma unroll
    for (int k = 0; k < 16; k++) {
        float lo, hi;
        unpack2(xpa[k], lo, hi); fa[k] = lo; ga[k] = hi;
        unpack2(xpb[k], lo, hi); fb[k] = lo; gb[k] = hi;
    }
    if (v0) {
        #pragma unroll
        for (int q = 0; q < 4; q++) {
            g_bufA[n0 * 4 + q] = make_float4(
                A0 * fa[4 * q + 0] + B0 * fb[4 * q + 0],
                A0 * fa[4 * q + 1] + B0 * fb[4 * q + 1],
                A0 * fa[4 * q + 2] + B0 * fb[4 * q + 2],
                A0 * fa[4 * q + 3] + B0 * fb[4 * q + 3]);
        }
    }
    if (v1) {
        #pragma unroll
        for (int q = 0; q < 4; q++) {
            g_bufA[n1 * 4 + q] = make_float4(
                A1 * ga[4 * q + 0] + B1 * gb[4 * q + 0],
                A1 * ga[4 * q + 1] + B1 * gb[4 * q + 1],
                A1 * ga[4 * q + 2] + B1 * gb[4 * q + 2],
                A1 * ga[4 * q + 3] + B1 * gb[4 * q + 3]);
        }
    }
}

// ---------------- launch ----------------
extern "C" void kernel_launch(void* const* d_in, const int* in_sizes, int n_in,
                              void* d_out, int out_size) {
    int is64 = (in_sizes[1] >= 4 * NE) ? 1 : 0;

    const int NB_N  = (NN + 255) / 256;
    const int NB_E  = (NE + 255) / 256;
    const int NB_SC = (NN + 1023) / 1024;
    const int NB_W  = (NN + 7) / 8;
    const int NB_L  = (NN + 255) / 256;

    cudaFuncSetAttribute(k_lstm, cudaFuncAttributeMaxDynamicSharedMemorySize, SMEM_LSTM);
    cudaFuncSetAttribute(k_gemm1, cudaFuncAttributeMaxDynamicSharedMemorySize, SMEM_G1);

    k_zero<<<NB_N, 256>>>();
    k_count<<<NB_E, 256>>>((const int*)d_in[1], is64);
    k_dinv<<<NB_N, 256>>>();
    k_gemm1<<<NB_N, 256, SMEM_G1>>>((const float4*)d_in[0], (const float*)d_in[2]);
    k_scanA<<<NB_SC, 1024>>>();
    k_scanB<<<1, 128>>>(NB_SC);
    k_scanC<<<NB_N, 256>>>();
    k_scatter<<<NB_E, 256>>>();

    k_agg<0><<<NB_W, 256>>>(nullptr, (const float*)d_in[3], (const float4*)d_in[4], nullptr);
    k_agg<1><<<NB_W, 256>>>(nullptr, (const float*)d_in[5], nullptr, nullptr);

    k_lstm<<<NB_L, 128, SMEM_LSTM>>>(
        (const float4*)d_in[6], (const float4*)d_in[7], (const float*)d_in[8],
        (const float4*)d_in[9], (const float4*)d_in[10], (const float*)d_in[11],
        (const float*)d_in[12], (const float*)d_in[13]);

    k_agg<2><<<NB_W, 256>>>((float*)d_out, nullptr, (const float4*)d_in[14],
                            (const float*)d_in[15]);
}

// round 14
// speedup vs baseline: 1.0232x; 1.0200x over previous
#include <cuda_runtime.h>
#include <cstdint>

#define NN 100000
#define NE 3200000

typedef unsigned long long ull;

// ---------------- device scratch ----------------
__device__ int2   g_edges[NE];      // (src, norm-as-float-bits), CSR by dst
__device__ int    g_cnt[NN];
__device__ int    g_rowptr[NN + 1];
__device__ int    g_cursor[NN];
__device__ int    g_bsum[128];
__device__ int    g_bsumEx[128];
__device__ float  g_dinv[NN];
__device__ float4 g_bufA[NN * 4];   // xw  -> (reused) H
__device__ float4 g_bufC[NN * 4];   // xw2
__device__ float4 g_x1[NN * 4];
__device__ float4 g_x2[NN * 4];

// ---------------- helpers ----------------
__device__ __forceinline__ float sigm_f(float x) {
    return __fdividef(1.0f, 1.0f + __expf(-x));
}
__device__ __forceinline__ float tanh_f(float x) {
    float e = __expf(2.0f * x);
    return 1.0f - __fdividef(2.0f, e + 1.0f);
}
__device__ __forceinline__ ull pack2(float a, float b) {
    ull r;
    asm("mov.b64 %0, {%1, %2};" : "=l"(r) : "f"(a), "f"(b));
    return r;
}
__device__ __forceinline__ ull fma2(ull a, ull b, ull c) {
    ull d;
    asm("fma.rn.f32x2 %0, %1, %2, %3;" : "=l"(d) : "l"(a), "l"(b), "l"(c));
    return d;
}
__device__ __forceinline__ void unpack2(ull v, float& a, float& b) {
    asm("mov.b64 {%0, %1}, %2;" : "=f"(a), "=f"(b) : "l"(v));
}
#define FMA2W(acc, w, xv) (acc) = fma2(pack2((w), (w)), (xv), (acc))

#define CP16(dst, src) \
    asm volatile("cp.async.cg.shared.global [%0], [%1], 16;" :: "r"(dst), "l"(src))
#define CPCOMMIT() asm volatile("cp.async.commit_group;")
#define CPWAIT(n)  asm volatile("cp.async.wait_group %0;" :: "n"(n))

// ---------------- graph preprocessing (slimmed: no src/dst staging) -------------
__global__ void k_zero() {
    int i = blockIdx.x * blockDim.x + threadIdx.x;
    if (i < NN) g_cnt[i] = 0;
}

__global__ void k_count(const int* __restrict__ ei, int is64) {
    int e = blockIdx.x * blockDim.x + threadIdx.x;
    if (e >= NE) return;
    int d = is64 ? ei[2 * (NE + e)] : ei[NE + e];
    atomicAdd(&g_cnt[d], 1);
}

__global__ void k_scanA() {
    __shared__ int sh[1024];
    int i = blockIdx.x * 1024 + threadIdx.x;
    int v = (i < NN) ? g_cnt[i] : 0;
    sh[threadIdx.x] = v;
    __syncthreads();
    #pragma unroll
    for (int off = 1; off < 1024; off <<= 1) {
        int t = (threadIdx.x >= off) ? sh[threadIdx.x - off] : 0;
        __syncthreads();
        sh[threadIdx.x] += t;
        __syncthreads();
    }
    if (i < NN) {
        g_rowptr[i] = sh[threadIdx.x] - v;  // exclusive
        g_dinv[i] = rsqrtf((float)v + 1.0f);
    }
    if (threadIdx.x == 1023) g_bsum[blockIdx.x] = sh[1023];
}

__global__ void k_scanB(int nb) {
    __shared__ int sh[128];
    int t = threadIdx.x;
    int v = (t < nb) ? g_bsum[t] : 0;
    sh[t] = v;
    __syncthreads();
    #pragma unroll
    for (int off = 1; off < 128; off <<= 1) {
        int tv = (t >= off) ? sh[t - off] : 0;
        __syncthreads();
        sh[t] += tv;
        __syncthreads();
    }
    g_bsumEx[t] = sh[t] - v;
}

__global__ void k_scanC() {
    int i = blockIdx.x * blockDim.x + threadIdx.x;
    if (i < NN) {
        int r = g_rowptr[i] + g_bsumEx[i >> 10];
        g_rowptr[i] = r;
        g_cursor[i] = r;
    }
    if (i == 0) g_rowptr[NN] = NE;
}

__global__ void k_scatter(const int* __restrict__ ei, int is64) {
    int e = blockIdx.x * blockDim.x + threadIdx.x;
    if (e >= NE) return;
    int s, d;
    if (is64) {
        s = ei[2 * e];
        d = ei[2 * (NE + e)];
    } else {
        s = ei[e];
        d = ei[NE + e];
    }
    int p = atomicAdd(&g_cursor[d], 1);
    g_edges[p] = make_int2(s, __float_as_int(g_dinv[s] * g_dinv[d]));
}

// ---------------- GEMM1 (round-8 exact: measured 76.6us) ------------------------
// cp.async double-buffered, W1 fully smem-resident. Block = 256 thr, 256 rows.
#define G1_XS_BYTES   73728            // 2 * 256 * 36 * 4
#define G1_BUF_FLOATS 9216             // 256 * 36
#define SMEM_G1       (G1_XS_BYTES + 32768)

__global__ void __launch_bounds__(256) k_gemm1(const float4* __restrict__ x4,
                                               const float* __restrict__ w) {
    extern __shared__ char g1sm[];
    float*      xs  = (float*)g1sm;
    ulonglong2* sws = (ulonglong2*)(g1sm + G1_XS_BYTES);

    int tid = threadIdx.x;
    int c4  = tid & 7;
    int r0  = tid >> 3;

    const ulonglong2* w16 = (const ulonglong2*)w;
    #pragma unroll
    for (int i = 0; i < 8; i++) sws[i * 256 + tid] = w16[i * 256 + tid];

    const float4* src[8];
    #pragma unroll
    for (int j = 0; j < 8; j++) {
        int gr = blockIdx.x * 256 + j * 32 + r0;
        if (gr >= NN) gr = NN - 1;
        src[j] = x4 + gr * 128 + c4;
    }
    unsigned int xs_u = (unsigned int)__cvta_generic_to_shared(xs);
    unsigned int dst0 = xs_u + (unsigned int)(r0 * 144 + c4 * 16);

    #pragma unroll
    for (int j = 0; j < 8; j++) CP16(dst0 + j * 32 * 144, src[j] + 0 * 8);
    CPCOMMIT();
    #pragma unroll
    for (int j = 0; j < 8; j++) CP16(dst0 + G1_XS_BYTES / 2 + j * 32 * 144, src[j] + 1 * 8);
    CPCOMMIT();

    ull acc2[8];
    #pragma unroll
    for (int p = 0; p < 8; p++) acc2[p] = 0ULL;

    #pragma unroll 1
    for (int kc = 0; kc < 16; kc++) {
        if (kc < 15) { CPWAIT(1); } else { CPWAIT(0); }
        __syncthreads();

        const float* xb = xs + (kc & 1) * G1_BUF_FLOATS + tid * 36;
        #pragma unroll
        for (int q = 0; q < 8; q++) {
            float4 xv = *(const float4*)(xb + q * 4);
            const ulonglong2* wp = sws + (kc * 32 + q * 4) * 4;
            {
                ull xd = pack2(xv.x, xv.x);
                ulonglong2 a = wp[0], b = wp[1], c = wp[2], d = wp[3];
                acc2[0] = fma2(a.x, xd, acc2[0]); acc2[1] = fma2(a.y, xd, acc2[1]);
                acc2[2] = fma2(b.x, xd, acc2[2]); acc2[3] = fma2(b.y, xd, acc2[3]);
                acc2[4] = fma2(c.x, xd, acc2[4]); acc2[5] = fma2(c.y, xd, acc2[5]);
                acc2[6] = fma2(d.x, xd, acc2[6]); acc2[7] = fma2(d.y, xd, acc2[7]);
            }
            {
                ull xd = pack2(xv.y, xv.y);
                ulonglong2 a = wp[4], b = wp[5], c = wp[6], d = wp[7];
                acc2[0] = fma2(a.x, xd, acc2[0]); acc2[1] = fma2(a.y, xd, acc2[1]);
                acc2[2] = fma2(b.x, xd, acc2[2]); acc2[3] = fma2(b.y, xd, acc2[3]);
                acc2[4] = fma2(c.x, xd, acc2[4]); acc2[5] = fma2(c.y, xd, acc2[5]);
                acc2[6] = fma2(d.x, xd, acc2[6]); acc2[7] = fma2(d.y, xd, acc2[7]);
            }
            {
                ull xd = pack2(xv.z, xv.z);
                ulonglong2 a = wp[8], b = wp[9], c = wp[10], d = wp[11];
                acc2[0] = fma2(a.x, xd, acc2[0]); acc2[1] = fma2(a.y, xd, acc2[1]);
                acc2[2] = fma2(b.x, xd, acc2[2]); acc2[3] = fma2(b.y, xd, acc2[3]);
                acc2[4] = fma2(c.x, xd, acc2[4]); acc2[5] = fma2(c.y, xd, acc2[5]);
                acc2[6] = fma2(d.x, xd, acc2[6]); acc2[7] = fma2(d.y, xd, acc2[7]);
            }
            {
                ull xd = pack2(xv.w, xv.w);
                ulonglong2 a = wp[12], b = wp[13], c = wp[14], d = wp[15];
                acc2[0] = fma2(a.x, xd, acc2[0]); acc2[1] = fma2(a.y, xd, acc2[1]);
                acc2[2] = fma2(b.x, xd, acc2[2]); acc2[3] = fma2(b.y, xd, acc2[3]);
                acc2[4] = fma2(c.x, xd, acc2[4]); acc2[5] = fma2(c.y, xd, acc2[5]);
                acc2[6] = fma2(d.x, xd, acc2[6]); acc2[7] = fma2(d.y, xd, acc2[7]);
            }
        }
        __syncthreads();
        if (kc < 14) {
            unsigned int db = dst0 + (kc & 1) * (G1_XS_BYTES / 2);
            #pragma unroll
            for (int j = 0; j < 8; j++) CP16(db + j * 32 * 144, src[j] + (kc + 2) * 8);
            CPCOMMIT();
        }
    }

    int row = blockIdx.x * 256 + tid;
    if (row < NN) {
        float o[16];
        #pragma unroll
        for (int p = 0; p < 8; p++) unpack2(acc2[p], o[2 * p], o[2 * p + 1]);
        g_bufA[row * 4 + 0] = make_float4(o[0],  o[1],  o[2],  o[3]);
        g_bufA[row * 4 + 1] = make_float4(o[4],  o[5],  o[6],  o[7]);
        g_bufA[row * 4 + 2] = make_float4(o[8],  o[9],  o[10], o[11]);
        g_bufA[row * 4 + 3] = make_float4(o[12], o[13], o[14], o[15]);
    }
}

// ---------------- GCN aggregation: warp-per-node, 4 lanes per edge --------------
template <int MODE>
__global__ void __launch_bounds__(256) k_agg(float* __restrict__ outp,
                                             const float* __restrict__ bias,
                                             const float4* __restrict__ W4,
                                             const float* __restrict__ Wb) {
    __shared__ float4 sW[160];
    __shared__ float  sx[8][16];
    if (MODE == 0) { if (threadIdx.x < 64)  sW[threadIdx.x] = W4[threadIdx.x]; }
    if (MODE == 2) { if (threadIdx.x < 160) sW[threadIdx.x] = W4[threadIdx.x]; }
    __syncthreads();

    int warp = threadIdx.x >> 5;
    int lane = threadIdx.x & 31;
    int g = lane >> 2, q = lane & 3;
    int n = blockIdx.x * 8 + warp;
    if (n >= NN) return;

    const float4* in4 = (MODE == 1) ? g_bufC : g_bufA;

    float4 acc = make_float4(0.f, 0.f, 0.f, 0.f);
    if (g == 0) {
        float dd = g_dinv[n]; dd *= dd;
        float4 a = in4[n * 4 + q];
        acc.x = dd * a.x; acc.y = dd * a.y; acc.z = dd * a.z; acc.w = dd * a.w;
    }

    int beg = g_rowptr[n], end = g_rowptr[n + 1];
    for (int e = beg + g; e < end; e += 8) {
        int2 ev = g_edges[e];
        float w = __int_as_float(ev.y);
        float4 v = in4[ev.x * 4 + q];
        acc.x += w * v.x; acc.y += w * v.y; acc.z += w * v.z; acc.w += w * v.w;
    }

    #pragma unroll
    for (int off = 4; off < 32; off <<= 1) {
        acc.x += __shfl_xor_sync(0xffffffffu, acc.x, off);
        acc.y += __shfl_xor_sync(0xffffffffu, acc.y, off);
        acc.z += __shfl_xor_sync(0xffffffffu, acc.z, off);
        acc.w += __shfl_xor_sync(0xffffffffu, acc.w, off);
    }

    if (MODE == 0 || MODE == 1) {
        if (g == 0) {
            float4 b = ((const float4*)bias)[q];
            float4 xr;
            xr.x = fmaxf(acc.x + b.x, 0.0f);
            xr.y = fmaxf(acc.y + b.y, 0.0f);
            xr.z = fmaxf(acc.z + b.z, 0.0f);
            xr.w = fmaxf(acc.w + b.w, 0.0f);
            float4* ox = (MODE == 0) ? (g_x1 + n * 4) : (g_x2 + n * 4);
            ox[q] = xr;
            if (MODE == 0) {
                sx[warp][q * 4 + 0] = xr.x; sx[warp][q * 4 + 1] = xr.y;
                sx[warp][q * 4 + 2] = xr.z; sx[warp][q * 4 + 3] = xr.w;
            }
        }
        if (MODE == 0) {
            __syncwarp();
            if (g == 0) {
                float y[4] = {0.f, 0.f, 0.f, 0.f};
                #pragma unroll
                for (int k = 0; k < 16; k++) {
                    float xv = sx[warp][k];
                    float4 w = sW[k * 4 + q];
                    y[0] += xv * w.x; y[1] += xv * w.y;
                    y[2] += xv * w.z; y[3] += xv * w.w;
                }
                g_bufC[n * 4 + q] = make_float4(y[0], y[1], y[2], y[3]);
            }
        }
    } else {  // MODE 2
        if (g == 0) {
            sx[warp][q * 4 + 0] = acc.x; sx[warp][q * 4 + 1] = acc.y;
            sx[warp][q * 4 + 2] = acc.z; sx[warp][q * 4 + 3] = acc.w;
        }
        __syncwarp();
        const float* sWf = (const float*)sW;
        float v0 = __ldg(&Wb[lane]);
        float v1 = (lane < 8) ? __ldg(&Wb[32 + lane]) : -1e30f;
        #pragma unroll
        for (int k = 0; k < 16; k++) {
            float a = sx[warp][k];
            v0 += a * sWf[k * 40 + lane];
            if (lane < 8) v1 += a * sWf[k * 40 + 32 + lane];
        }
        float m = fmaxf(v0, v1);
        #pragma unroll
        for (int off = 1; off < 32; off <<= 1)
            m = fmaxf(m, __shfl_xor_sync(0xffffffffu, m, off));
        float s = __expf(v0 - m) + ((lane < 8) ? __expf(v1 - m) : 0.0f);
        #pragma unroll
        for (int off = 1; off < 32; off <<= 1)
            s += __shfl_xor_sync(0xffffffffu, s, off);
        float lse = m + __logf(s);
        outp[n * 40 + lane] = v0 - lse;
        if (lane < 8) outp[n * 40 + 32 + lane] = v1 - lse;
    }
}

// ---------------- JK bidirectional LSTM (round-3 exact: 401.5us config) ---------
#define LS_SIHF 0        // float4[512]   8KB  w_ih_f
#define LS_SIHB 8192     // float4[512]   8KB  w_ih_b
#define LS_SHH  16384    // float4[1024] 16KB  w_hh (fwd, then bwd)
#define LS_BF   32768    // float[128]
#define LS_BB   33280    // float[128]
#define LS_AW   33792    // float[64]
#define LS_H    34048    // ull[32*128]  32KB
#define LS_C    66816    // ull[32*128]  32KB
#define SMEM_LSTM 99584

__device__ __forceinline__ void cell0p(const ull* __restrict__ xp,
                                       ull* __restrict__ hsh, ull* __restrict__ csh,
                                       const float4* __restrict__ sih,
                                       const float* __restrict__ sb,
                                       const float* __restrict__ sw, ull& sacc) {
    #pragma unroll 1
    for (int j = 0; j < 32; j++) {
        float bi = sb[j], bg = sb[64 + j], bo = sb[96 + j];
        ull ai = pack2(bi, bi), ag = pack2(bg, bg), ao = pack2(bo, bo);
        #pragma unroll
        for (int q = 0; q < 4; q++) {
            float4 wi = sih[j * 4 + q];
            FMA2W(ai, wi.x, xp[4 * q + 0]); FMA2W(ai, wi.y, xp[4 * q + 1]);
            FMA2W(ai, wi.z, xp[4 * q + 2]); FMA2W(ai, wi.w, xp[4 * q + 3]);
            float4 wg = sih[(64 + j) * 4 + q];
            FMA2W(ag, wg.x, xp[4 * q + 0]); FMA2W(ag, wg.y, xp[4 * q + 1]);
            FMA2W(ag, wg.z, xp[4 * q + 2]); FMA2W(ag, wg.w, xp[4 * q + 3]);
            float4 wo = sih[(96 + j) * 4 + q];
            FMA2W(ao, wo.x, xp[4 * q + 0]); FMA2W(ao, wo.y, xp[4 * q + 1]);
            FMA2W(ao, wo.z, xp[4 * q + 2]); FMA2W(ao, wo.w, xp[4 * q + 3]);
        }
        float i0, i1, g0, g1, o0, o1;
        unpack2(ai, i0, i1); unpack2(ag, g0, g1); unpack2(ao, o0, o1);
        float c0 = sigm_f(i0) * tanh_f(g0), c1 = sigm_f(i1) * tanh_f(g1);
        float h0 = sigm_f(o0) * tanh_f(c0), h1 = sigm_f(o1) * tanh_f(c1);
        csh[j * 128] = pack2(c0, c1);
        ull hp = pack2(h0, h1);
        hsh[j * 128] = hp;
        float awj = sw[j];
        sacc = fma2(hp, pack2(awj, awj), sacc);
    }
}

__device__ __forceinline__ void cell1p(const ull* __restrict__ xp,
                                       const ull* __restrict__ hreg,
                                       const ull* __restrict__ csh,
                                       const float4* __restrict__ sih,
                                       const float4* __restrict__ shh,
                                       const float* __restrict__ sb,
                                       const float* __restrict__ sw, ull& sacc) {
    #pragma unroll 1
    for (int j = 0; j < 32; j++) {
        float bi = sb[j], bff = sb[32 + j], bg = sb[64 + j], bo = sb[96 + j];
        ull ai = pack2(bi, bi), af = pack2(bff, bff);
        ull ag = pack2(bg, bg), ao = pack2(bo, bo);
        #pragma unroll
        for (int q = 0; q < 4; q++) {
            float4 wi = sih[j * 4 + q];
            FMA2W(ai, wi.x, xp[4 * q + 0]); FMA2W(ai, wi.y, xp[4 * q + 1]);
            FMA2W(ai, wi.z, xp[4 * q + 2]); FMA2W(ai, wi.w, xp[4 * q + 3]);
            float4 wf = sih[(32 + j) * 4 + q];
            FMA2W(af, wf.x, xp[4 * q + 0]); FMA2W(af, wf.y, xp[4 * q + 1]);
            FMA2W(af, wf.z, xp[4 * q + 2]); FMA2W(af, wf.w, xp[4 * q + 3]);
            float4 wg = sih[(64 + j) * 4 + q];
            FMA2W(ag, wg.x, xp[4 * q + 0]); FMA2W(ag, wg.y, xp[4 * q + 1]);
            FMA2W(ag, wg.z, xp[4 * q + 2]); FMA2W(ag, wg.w, xp[4 * q + 3]);
            float4 wo = sih[(96 + j) * 4 + q];
            FMA2W(ao, wo.x, xp[4 * q + 0]); FMA2W(ao, wo.y, xp[4 * q + 1]);
            FMA2W(ao, wo.z, xp[4 * q + 2]); FMA2W(ao, wo.w, xp[4 * q + 3]);
        }
        #pragma unroll
        for (int q = 0; q < 8; q++) {
            float4 wi = shh[j * 8 + q];
            FMA2W(ai, wi.x, hreg[4 * q + 0]); FMA2W(ai, wi.y, hreg[4 * q + 1]);
            FMA2W(ai, wi.z, hreg[4 * q + 2]); FMA2W(ai, wi.w, hreg[4 * q + 3]);
            float4 wf = shh[(32 + j) * 8 + q];
            FMA2W(af, wf.x, hreg[4 * q + 0]); FMA2W(af, wf.y, hreg[4 * q + 1]);
            FMA2W(af, wf.z, hreg[4 * q + 2]); FMA2W(af, wf.w, hreg[4 * q + 3]);
            float4 wg = shh[(64 + j) * 8 + q];
            FMA2W(ag, wg.x, hreg[4 * q + 0]); FMA2W(ag, wg.y, hreg[4 * q + 1]);
            FMA2W(ag, wg.z, hreg[4 * q + 2]); FMA2W(ag, wg.w, hreg[4 * q + 3]);
            float4 wo = shh[(96 + j) * 8 + q];
            FMA2W(ao, wo.x, hreg[4 * q + 0]); FMA2W(ao, wo.y, hreg[4 * q + 1]);
            FMA2W(ao, wo.z, hreg[4 * q + 2]); FMA2W(ao, wo.w, hreg[4 * q + 3]);
        }
        float i0, i1, f0, f1, g0, g1, o0, o1;
        unpack2(ai, i0, i1); unpack2(af, f0, f1);
        unpack2(ag, g0, g1); unpack2(ao, o0, o1);
        float cp0, cp1;
        unpack2(csh[j * 128], cp0, cp1);
        float c0 = sigm_f(f0) * cp0 + sigm_f(i0) * tanh_f(g0);
        float c1 = sigm_f(f1) * cp1 + sigm_f(i1) * tanh_f(g1);
        float h0 = sigm_f(o0) * tanh_f(c0), h1 = sigm_f(o1) * tanh_f(c1);
        float awj = sw[j];
        sacc = fma2(pack2(h0, h1), pack2(awj, awj), sacc);
    }
}

__global__ void __launch_bounds__(128, 2) k_lstm(
    const float4* __restrict__ wihf, const float4* __restrict__ whhf, const float* __restrict__ bf,
    const float4* __restrict__ wihb, const float4* __restrict__ whhb, const float* __restrict__ bb,
    const float* __restrict__ aw, const float* __restrict__ ab) {
    extern __shared__ char sm[];
    float4* sihf = (float4*)(sm + LS_SIHF);
    float4* sihb = (float4*)(sm + LS_SIHB);
    float4* shh  = (float4*)(sm + LS_SHH);
    float*  sbf  = (float*)(sm + LS_BF);
    float*  sbb  = (float*)(sm + LS_BB);
    float*  saw  = (float*)(sm + LS_AW);
    int tid = threadIdx.x;
    ull* hsh = (ull*)(sm + LS_H) + tid;
    ull* csh = (ull*)(sm + LS_C) + tid;

    for (int i = tid; i < 512; i += 128) { sihf[i] = wihf[i]; sihb[i] = wihb[i]; }
    for (int i = tid; i < 1024; i += 128) shh[i] = whhf[i];
    if (tid < 64) {
        sbf[tid] = bf[tid]; sbf[64 + tid] = bf[64 + tid];
        sbb[tid] = bb[tid]; sbb[64 + tid] = bb[64 + tid];
        saw[tid] = aw[tid];
    }
    __syncthreads();

    int n0 = blockIdx.x * 256 + tid;
    int n1 = n0 + 128;
    bool v0 = n0 < NN, v1 = n1 < NN;
    int m0 = v0 ? n0 : 0, m1 = v1 ? n1 : 0;

    ull xpa[16], xpb[16];
    {
        #pragma unroll
        for (int q = 0; q < 4; q++) {
            float4 a = g_x1[m0 * 4 + q], b = g_x1[m1 * 4 + q];
            xpa[4 * q + 0] = pack2(a.x, b.x); xpa[4 * q + 1] = pack2(a.y, b.y);
            xpa[4 * q + 2] = pack2(a.z, b.z); xpa[4 * q + 3] = pack2(a.w, b.w);
            float4 c = g_x2[m0 * 4 + q], d = g_x2[m1 * 4 + q];
            xpb[4 * q + 0] = pack2(c.x, d.x); xpb[4 * q + 1] = pack2(c.y, d.y);
            xpb[4 * q + 2] = pack2(c.z, d.z); xpb[4 * q + 3] = pack2(c.w, d.w);
        }
    }

    ull s0 = 0ULL, s1 = 0ULL;
    ull hreg[32];

    cell0p(xpa, hsh, csh, sihf, sbf, saw, s0);
    #pragma unroll
    for (int k = 0; k < 32; k++) hreg[k] = hsh[k * 128];
    cell1p(xpb, hreg, csh, sihf, shh, sbf, saw, s1);

    __syncthreads();
    for (int i = tid; i < 1024; i += 128) shh[i] = whhb[i];
    __syncthreads();

    cell0p(xpb, hsh, csh, sihb, sbb, saw + 32, s1);
    #pragma unroll
    for (int k = 0; k < 32; k++) hreg[k] = hsh[k * 128];
    cell1p(xpa, hreg, csh, sihb, shh, sbb, saw + 32, s0);

    float abv = __ldg(ab);
    float s00, s01, s10, s11;
    unpack2(s0, s00, s01); unpack2(s1, s10, s11);
    s00 += abv; s01 += abv; s10 += abv; s11 += abv;

    float mA = fmaxf(s00, s10);
    float eA0 = __expf(s00 - mA), eA1 = __expf(s10 - mA);
    float invA = __fdividef(1.0f, eA0 + eA1);
    float A0 = eA0 * invA, B0 = eA1 * invA;

    float mB = fmaxf(s01, s11);
    float eB0 = __expf(s01 - mB), eB1 = __expf(s11 - mB);
    float invB = __fdividef(1.0f, eB0 + eB1);
    float A1 = eB0 * invB, B1 = eB1 * invB;

    float fa[16], fb[16], ga[16], gb[16];
    #pragma unroll
    for (int k = 0; k < 16; k++) {
        float lo, hi;
        unpack2(xpa[k], lo, hi); fa[k] = lo; ga[k] = hi;
        unpack2(xpb[k], lo, hi); fb[k] = lo; gb[k] = hi;
    }
    if (v0) {
        #pragma unroll
        for (int q = 0; q < 4; q++) {
            g_bufA[n0 * 4 + q] = make_float4(
                A0 * fa[4 * q + 0] + B0 * fb[4 * q + 0],
                A0 * fa[4 * q + 1] + B0 * fb[4 * q + 1],
                A0 * fa[4 * q + 2] + B0 * fb[4 * q + 2],
                A0 * fa[4 * q + 3] + B0 * fb[4 * q + 3]);
        }
    }
    if (v1) {
        #pragma unroll
        for (int q = 0; q < 4; q++) {
            g_bufA[n1 * 4 + q] = make_float4(
                A1 * ga[4 * q + 0] + B1 * gb[4 * q + 0],
                A1 * ga[4 * q + 1] + B1 * gb[4 * q + 1],
                A1 * ga[4 * q + 2] + B1 * gb[4 * q + 2],
                A1 * ga[4 * q + 3] + B1 * gb[4 * q + 3]);
        }
    }
}

// ---------------- launch ----------------
extern "C" void kernel_launch(void* const* d_in, const int* in_sizes, int n_in,
                              void* d_out, int out_size) {
    int is64 = (in_sizes[1] >= 4 * NE) ? 1 : 0;

    const int NB_N  = (NN + 255) / 256;
    const int NB_E  = (NE + 255) / 256;
    const int NB_SC = (NN + 1023) / 1024;
    const int NB_W  = (NN + 7) / 8;
    const int NB_L  = (NN + 255) / 256;

    cudaFuncSetAttribute(k_lstm, cudaFuncAttributeMaxDynamicSharedMemorySize, SMEM_LSTM);
    cudaFuncSetAttribute(k_gemm1, cudaFuncAttributeMaxDynamicSharedMemorySize, SMEM_G1);

    // gemm1 kept in the profiled 4th slot
    k_zero<<<NB_N, 256>>>();
    k_count<<<NB_E, 256>>>((const int*)d_in[1], is64);
    k_scanA<<<NB_SC, 1024>>>();
    k_gemm1<<<NB_N, 256, SMEM_G1>>>((const float4*)d_in[0], (const float*)d_in[2]);
    k_scanB<<<1, 128>>>(NB_SC);
    k_scanC<<<NB_N, 256>>>();
    k_scatter<<<NB_E, 256>>>((const int*)d_in[1], is64);

    k_agg<0><<<NB_W, 256>>>(nullptr, (const float*)d_in[3], (const float4*)d_in[4], nullptr);
    k_agg<1><<<NB_W, 256>>>(nullptr, (const float*)d_in[5], nullptr, nullptr);

    k_lstm<<<NB_L, 128, SMEM_LSTM>>>(
        (const float4*)d_in[6], (const float4*)d_in[7], (const float*)d_in[8],
        (const float4*)d_in[9], (const float4*)d_in[10], (const float*)d_in[11],
        (const float*)d_in[12], (const float*)d_in[13]);

    k_agg<2><<<NB_W, 256>>>((float*)d_out, nullptr, (const float4*)d_in[14],
                            (const float*)d_in[15]);
}

// round 15
// speedup vs baseline: 1.0608x; 1.0367x over previous
#include <cuda_runtime.h>
#include <cstdint>

#define NN 100000
#define NE 3200000

typedef unsigned long long ull;

// ---------------- device scratch ----------------
__device__ int2   g_edges[NE];      // (src, norm-as-float-bits), CSR by dst
__device__ int    g_cnt[NN];
__device__ int    g_rowptr[NN + 1];
__device__ int    g_cursor[NN];
__device__ int    g_bsum[128];
__device__ int    g_bsumEx[128];
__device__ float  g_dinv[NN];
__device__ float4 g_bufA[NN * 4];   // xw  -> (reused) H
__device__ float4 g_bufC[NN * 4];   // xw2
__device__ float4 g_x1[NN * 4];
__device__ float4 g_x2[NN * 4];

// ---------------- helpers ----------------
__device__ __forceinline__ float tanh_a(float x) {
    float r;
    asm("tanh.approx.f32 %0, %1;" : "=f"(r) : "f"(x));
    return r;
}
__device__ __forceinline__ float sigm_a(float x) {
    return fmaf(0.5f, tanh_a(0.5f * x), 0.5f);
}
__device__ __forceinline__ ull pack2(float a, float b) {
    ull r;
    asm("mov.b64 %0, {%1, %2};" : "=l"(r) : "f"(a), "f"(b));
    return r;
}
__device__ __forceinline__ ull fma2(ull a, ull b, ull c) {
    ull d;
    asm("fma.rn.f32x2 %0, %1, %2, %3;" : "=l"(d) : "l"(a), "l"(b), "l"(c));
    return d;
}
__device__ __forceinline__ void unpack2(ull v, float& a, float& b) {
    asm("mov.b64 {%0, %1}, %2;" : "=f"(a), "=f"(b) : "l"(v));
}
#define FMA2W(acc, w, xv) (acc) = fma2(pack2((w), (w)), (xv), (acc))

#define CP16(dst, src) \
    asm volatile("cp.async.cg.shared.global [%0], [%1], 16;" :: "r"(dst), "l"(src))
#define CPCOMMIT() asm volatile("cp.async.commit_group;")
#define CPWAIT(n)  asm volatile("cp.async.wait_group %0;" :: "n"(n))

// ---------------- graph preprocessing (slimmed: no src/dst staging) -------------
__global__ void k_zero() {
    int i = blockIdx.x * blockDim.x + threadIdx.x;
    if (i < NN) g_cnt[i] = 0;
}

__global__ void k_count(const int* __restrict__ ei, int is64) {
    int e = blockIdx.x * blockDim.x + threadIdx.x;
    if (e >= NE) return;
    int d = is64 ? ei[2 * (NE + e)] : ei[NE + e];
    atomicAdd(&g_cnt[d], 1);
}

__global__ void k_scanA() {
    __shared__ int sh[1024];
    int i = blockIdx.x * 1024 + threadIdx.x;
    int v = (i < NN) ? g_cnt[i] : 0;
    sh[threadIdx.x] = v;
    __syncthreads();
    #pragma unroll
    for (int off = 1; off < 1024; off <<= 1) {
        int t = (threadIdx.x >= off) ? sh[threadIdx.x - off] : 0;
        __syncthreads();
        sh[threadIdx.x] += t;
        __syncthreads();
    }
    if (i < NN) {
        g_rowptr[i] = sh[threadIdx.x] - v;  // exclusive
        g_dinv[i] = rsqrtf((float)v + 1.0f);
    }
    if (threadIdx.x == 1023) g_bsum[blockIdx.x] = sh[1023];
}

__global__ void k_scanB(int nb) {
    __shared__ int sh[128];
    int t = threadIdx.x;
    int v = (t < nb) ? g_bsum[t] : 0;
    sh[t] = v;
    __syncthreads();
    #pragma unroll
    for (int off = 1; off < 128; off <<= 1) {
        int tv = (t >= off) ? sh[t - off] : 0;
        __syncthreads();
        sh[t] += tv;
        __syncthreads();
    }
    g_bsumEx[t] = sh[t] - v;
}

__global__ void k_scanC() {
    int i = blockIdx.x * blockDim.x + threadIdx.x;
    if (i < NN) {
        int r = g_rowptr[i] + g_bsumEx[i >> 10];
        g_rowptr[i] = r;
        g_cursor[i] = r;
    }
    if (i == 0) g_rowptr[NN] = NE;
}

__global__ void k_scatter(const int* __restrict__ ei, int is64) {
    int e = blockIdx.x * blockDim.x + threadIdx.x;
    if (e >= NE) return;
    int s, d;
    if (is64) {
        s = ei[2 * e];
        d = ei[2 * (NE + e)];
    } else {
        s = ei[e];
        d = ei[NE + e];
    }
    int p = atomicAdd(&g_cursor[d], 1);
    g_edges[p] = make_int2(s, __float_as_int(g_dinv[s] * g_dinv[d]));
}

// ---------------- GEMM1 (round-8 exact: measured 76.6us) ------------------------
#define G1_XS_BYTES   73728            // 2 * 256 * 36 * 4
#define G1_BUF_FLOATS 9216             // 256 * 36
#define SMEM_G1       (G1_XS_BYTES + 32768)

__global__ void __launch_bounds__(256) k_gemm1(const float4* __restrict__ x4,
                                               const float* __restrict__ w) {
    extern __shared__ char g1sm[];
    float*      xs  = (float*)g1sm;
    ulonglong2* sws = (ulonglong2*)(g1sm + G1_XS_BYTES);

    int tid = threadIdx.x;
    int c4  = tid & 7;
    int r0  = tid >> 3;

    const ulonglong2* w16 = (const ulonglong2*)w;
    #pragma unroll
    for (int i = 0; i < 8; i++) sws[i * 256 + tid] = w16[i * 256 + tid];

    const float4* src[8];
    #pragma unroll
    for (int j = 0; j < 8; j++) {
        int gr = blockIdx.x * 256 + j * 32 + r0;
        if (gr >= NN) gr = NN - 1;
        src[j] = x4 + gr * 128 + c4;
    }
    unsigned int xs_u = (unsigned int)__cvta_generic_to_shared(xs);
    unsigned int dst0 = xs_u + (unsigned int)(r0 * 144 + c4 * 16);

    #pragma unroll
    for (int j = 0; j < 8; j++) CP16(dst0 + j * 32 * 144, src[j] + 0 * 8);
    CPCOMMIT();
    #pragma unroll
    for (int j = 0; j < 8; j++) CP16(dst0 + G1_XS_BYTES / 2 + j * 32 * 144, src[j] + 1 * 8);
    CPCOMMIT();

    ull acc2[8];
    #pragma unroll
    for (int p = 0; p < 8; p++) acc2[p] = 0ULL;

    #pragma unroll 1
    for (int kc = 0; kc < 16; kc++) {
        if (kc < 15) { CPWAIT(1); } else { CPWAIT(0); }
        __syncthreads();

        const float* xb = xs + (kc & 1) * G1_BUF_FLOATS + tid * 36;
        #pragma unroll
        for (int q = 0; q < 8; q++) {
            float4 xv = *(const float4*)(xb + q * 4);
            const ulonglong2* wp = sws + (kc * 32 + q * 4) * 4;
            {
                ull xd = pack2(xv.x, xv.x);
                ulonglong2 a = wp[0], b = wp[1], c = wp[2], d = wp[3];
                acc2[0] = fma2(a.x, xd, acc2[0]); acc2[1] = fma2(a.y, xd, acc2[1]);
                acc2[2] = fma2(b.x, xd, acc2[2]); acc2[3] = fma2(b.y, xd, acc2[3]);
                acc2[4] = fma2(c.x, xd, acc2[4]); acc2[5] = fma2(c.y, xd, acc2[5]);
                acc2[6] = fma2(d.x, xd, acc2[6]); acc2[7] = fma2(d.y, xd, acc2[7]);
            }
            {
                ull xd = pack2(xv.y, xv.y);
                ulonglong2 a = wp[4], b = wp[5], c = wp[6], d = wp[7];
                acc2[0] = fma2(a.x, xd, acc2[0]); acc2[1] = fma2(a.y, xd, acc2[1]);
                acc2[2] = fma2(b.x, xd, acc2[2]); acc2[3] = fma2(b.y, xd, acc2[3]);
                acc2[4] = fma2(c.x, xd, acc2[4]); acc2[5] = fma2(c.y, xd, acc2[5]);
                acc2[6] = fma2(d.x, xd, acc2[6]); acc2[7] = fma2(d.y, xd, acc2[7]);
            }
            {
                ull xd = pack2(xv.z, xv.z);
                ulonglong2 a = wp[8], b = wp[9], c = wp[10], d = wp[11];
                acc2[0] = fma2(a.x, xd, acc2[0]); acc2[1] = fma2(a.y, xd, acc2[1]);
                acc2[2] = fma2(b.x, xd, acc2[2]); acc2[3] = fma2(b.y, xd, acc2[3]);
                acc2[4] = fma2(c.x, xd, acc2[4]); acc2[5] = fma2(c.y, xd, acc2[5]);
                acc2[6] = fma2(d.x, xd, acc2[6]); acc2[7] = fma2(d.y, xd, acc2[7]);
            }
            {
                ull xd = pack2(xv.w, xv.w);
                ulonglong2 a = wp[12], b = wp[13], c = wp[14], d = wp[15];
                acc2[0] = fma2(a.x, xd, acc2[0]); acc2[1] = fma2(a.y, xd, acc2[1]);
                acc2[2] = fma2(b.x, xd, acc2[2]); acc2[3] = fma2(b.y, xd, acc2[3]);
                acc2[4] = fma2(c.x, xd, acc2[4]); acc2[5] = fma2(c.y, xd, acc2[5]);
                acc2[6] = fma2(d.x, xd, acc2[6]); acc2[7] = fma2(d.y, xd, acc2[7]);
            }
        }
        __syncthreads();
        if (kc < 14) {
            unsigned int db = dst0 + (kc & 1) * (G1_XS_BYTES / 2);
            #pragma unroll
            for (int j = 0; j < 8; j++) CP16(db + j * 32 * 144, src[j] + (kc + 2) * 8);
            CPCOMMIT();
        }
    }

    int row = blockIdx.x * 256 + tid;
    if (row < NN) {
        float o[16];
        #pragma unroll
        for (int p = 0; p < 8; p++) unpack2(acc2[p], o[2 * p], o[2 * p + 1]);
        g_bufA[row * 4 + 0] = make_float4(o[0],  o[1],  o[2],  o[3]);
        g_bufA[row * 4 + 1] = make_float4(o[4],  o[5],  o[6],  o[7]);
        g_bufA[row * 4 + 2] = make_float4(o[8],  o[9],  o[10], o[11]);
        g_bufA[row * 4 + 3] = make_float4(o[12], o[13], o[14], o[15]);
    }
}

// ---------------- GCN aggregation: warp-per-node, 4 lanes per edge --------------
template <int MODE>
__global__ void __launch_bounds__(256) k_agg(float* __restrict__ outp,
                                             const float* __restrict__ bias,
                                             const float4* __restrict__ W4,
                                             const float* __restrict__ Wb) {
    __shared__ float4 sW[160];
    __shared__ float  sx[8][16];
    if (MODE == 0) { if (threadIdx.x < 64)  sW[threadIdx.x] = W4[threadIdx.x]; }
    if (MODE == 2) { if (threadIdx.x < 160) sW[threadIdx.x] = W4[threadIdx.x]; }
    __syncthreads();

    int warp = threadIdx.x >> 5;
    int lane = threadIdx.x & 31;
    int g = lane >> 2, q = lane & 3;
    int n = blockIdx.x * 8 + warp;
    if (n >= NN) return;

    const float4* in4 = (MODE == 1) ? g_bufC : g_bufA;

    float4 acc = make_float4(0.f, 0.f, 0.f, 0.f);
    if (g == 0) {
        float dd = g_dinv[n]; dd *= dd;
        float4 a = in4[n * 4 + q];
        acc.x = dd * a.x; acc.y = dd * a.y; acc.z = dd * a.z; acc.w = dd * a.w;
    }

    int beg = g_rowptr[n], end = g_rowptr[n + 1];
    for (int e = beg + g; e < end; e += 8) {
        int2 ev = g_edges[e];
        float w = __int_as_float(ev.y);
        float4 v = in4[ev.x * 4 + q];
        acc.x += w * v.x; acc.y += w * v.y; acc.z += w * v.z; acc.w += w * v.w;
    }

    #pragma unroll
    for (int off = 4; off < 32; off <<= 1) {
        acc.x += __shfl_xor_sync(0xffffffffu, acc.x, off);
        acc.y += __shfl_xor_sync(0xffffffffu, acc.y, off);
        acc.z += __shfl_xor_sync(0xffffffffu, acc.z, off);
        acc.w += __shfl_xor_sync(0xffffffffu, acc.w, off);
    }

    if (MODE == 0 || MODE == 1) {
        if (g == 0) {
            float4 b = ((const float4*)bias)[q];
            float4 xr;
            xr.x = fmaxf(acc.x + b.x, 0.0f);
            xr.y = fmaxf(acc.y + b.y, 0.0f);
            xr.z = fmaxf(acc.z + b.z, 0.0f);
            xr.w = fmaxf(acc.w + b.w, 0.0f);
            float4* ox = (MODE == 0) ? (g_x1 + n * 4) : (g_x2 + n * 4);
            ox[q] = xr;
            if (MODE == 0) {
                sx[warp][q * 4 + 0] = xr.x; sx[warp][q * 4 + 1] = xr.y;
                sx[warp][q * 4 + 2] = xr.z; sx[warp][q * 4 + 3] = xr.w;
            }
        }
        if (MODE == 0) {
            __syncwarp();
            if (g == 0) {
                float y[4] = {0.f, 0.f, 0.f, 0.f};
                #pragma unroll
                for (int k = 0; k < 16; k++) {
                    float xv = sx[warp][k];
                    float4 w = sW[k * 4 + q];
                    y[0] += xv * w.x; y[1] += xv * w.y;
                    y[2] += xv * w.z; y[3] += xv * w.w;
                }
                g_bufC[n * 4 + q] = make_float4(y[0], y[1], y[2], y[3]);
            }
        }
    } else {  // MODE 2
        if (g == 0) {
            sx[warp][q * 4 + 0] = acc.x; sx[warp][q * 4 + 1] = acc.y;
            sx[warp][q * 4 + 2] = acc.z; sx[warp][q * 4 + 3] = acc.w;
        }
        __syncwarp();
        const float* sWf = (const float*)sW;
        float v0 = __ldg(&Wb[lane]);
        float v1 = (lane < 8) ? __ldg(&Wb[32 + lane]) : -1e30f;
        #pragma unroll
        for (int k = 0; k < 16; k++) {
            float a = sx[warp][k];
            v0 += a * sWf[k * 40 + lane];
            if (lane < 8) v1 += a * sWf[k * 40 + 32 + lane];
        }
        float m = fmaxf(v0, v1);
        #pragma unroll
        for (int off = 1; off < 32; off <<= 1)
            m = fmaxf(m, __shfl_xor_sync(0xffffffffu, m, off));
        float s = __expf(v0 - m) + ((lane < 8) ? __expf(v1 - m) : 0.0f);
        #pragma unroll
        for (int off = 1; off < 32; off <<= 1)
            s += __shfl_xor_sync(0xffffffffu, s, off);
        float lse = m + __logf(s);
        outp[n * 40 + lane] = v0 - lse;
        if (lane < 8) outp[n * 40 + 32 + lane] = v1 - lse;
    }
}

// ---------------- JK bidirectional LSTM (round-3 struct + tanh.approx) ----------
#define LS_SIHF 0        // float4[512]   8KB  w_ih_f
#define LS_SIHB 8192     // float4[512]   8KB  w_ih_b
#define LS_SHH  16384    // float4[1024] 16KB  w_hh (fwd, then bwd)
#define LS_BF   32768    // float[128]
#define LS_BB   33280    // float[128]
#define LS_AW   33792    // float[64]
#define LS_H    34048    // ull[32*128]  32KB
#define LS_C    66816    // ull[32*128]  32KB
#define SMEM_LSTM 99584

__device__ __forceinline__ void cell0p(const ull* __restrict__ xp,
                                       ull* __restrict__ hsh, ull* __restrict__ csh,
                                       const float4* __restrict__ sih,
                                       const float* __restrict__ sb,
                                       const float* __restrict__ sw, ull& sacc) {
    #pragma unroll 1
    for (int j = 0; j < 32; j++) {
        float bi = sb[j], bg = sb[64 + j], bo = sb[96 + j];
        ull ai = pack2(bi, bi), ag = pack2(bg, bg), ao = pack2(bo, bo);
        #pragma unroll
        for (int q = 0; q < 4; q++) {
            float4 wi = sih[j * 4 + q];
            FMA2W(ai, wi.x, xp[4 * q + 0]); FMA2W(ai, wi.y, xp[4 * q + 1]);
            FMA2W(ai, wi.z, xp[4 * q + 2]); FMA2W(ai, wi.w, xp[4 * q + 3]);
            float4 wg = sih[(64 + j) * 4 + q];
            FMA2W(ag, wg.x, xp[4 * q + 0]); FMA2W(ag, wg.y, xp[4 * q + 1]);
            FMA2W(ag, wg.z, xp[4 * q + 2]); FMA2W(ag, wg.w, xp[4 * q + 3]);
            float4 wo = sih[(96 + j) * 4 + q];
            FMA2W(ao, wo.x, xp[4 * q + 0]); FMA2W(ao, wo.y, xp[4 * q + 1]);
            FMA2W(ao, wo.z, xp[4 * q + 2]); FMA2W(ao, wo.w, xp[4 * q + 3]);
        }
        float i0, i1, g0, g1, o0, o1;
        unpack2(ai, i0, i1); unpack2(ag, g0, g1); unpack2(ao, o0, o1);
        float c0 = sigm_a(i0) * tanh_a(g0), c1 = sigm_a(i1) * tanh_a(g1);
        float h0 = sigm_a(o0) * tanh_a(c0), h1 = sigm_a(o1) * tanh_a(c1);
        csh[j * 128] = pack2(c0, c1);
        ull hp = pack2(h0, h1);
        hsh[j * 128] = hp;
        float awj = sw[j];
        sacc = fma2(hp, pack2(awj, awj), sacc);
    }
}

__device__ __forceinline__ void cell1p(const ull* __restrict__ xp,
                                       const ull* __restrict__ hreg,
                                       const ull* __restrict__ csh,
                                       const float4* __restrict__ sih,
                                       const float4* __restrict__ shh,
                                       const float* __restrict__ sb,
                                       const float* __restrict__ sw, ull& sacc) {
    #pragma unroll 1
    for (int j = 0; j < 32; j++) {
        float bi = sb[j], bff = sb[32 + j], bg = sb[64 + j], bo = sb[96 + j];
        ull ai = pack2(bi, bi), af = pack2(bff, bff);
        ull ag = pack2(bg, bg), ao = pack2(bo, bo);
        #pragma unroll
        for (int q = 0; q < 4; q++) {
            float4 wi = sih[j * 4 + q];
            FMA2W(ai, wi.x, xp[4 * q + 0]); FMA2W(ai, wi.y, xp[4 * q + 1]);
            FMA2W(ai, wi.z, xp[4 * q + 2]); FMA2W(ai, wi.w, xp[4 * q + 3]);
            float4 wf = sih[(32 + j) * 4 + q];
            FMA2W(af, wf.x, xp[4 * q + 0]); FMA2W(af, wf.y, xp[4 * q + 1]);
            FMA2W(af, wf.z, xp[4 * q + 2]); FMA2W(af, wf.w, xp[4 * q + 3]);
            float4 wg = sih[(64 + j) * 4 + q];
            FMA2W(ag, wg.x, xp[4 * q + 0]); FMA2W(ag, wg.y, xp[4 * q + 1]);
            FMA2W(ag, wg.z, xp[4 * q + 2]); FMA2W(ag, wg.w, xp[4 * q + 3]);
            float4 wo = sih[(96 + j) * 4 + q];
            FMA2W(ao, wo.x, xp[4 * q + 0]); FMA2W(ao, wo.y, xp[4 * q + 1]);
            FMA2W(ao, wo.z, xp[4 * q + 2]); FMA2W(ao, wo.w, xp[4 * q + 3]);
        }
        #pragma unroll
        for (int q = 0; q < 8; q++) {
            float4 wi = shh[j * 8 + q];
            FMA2W(ai, wi.x, hreg[4 * q + 0]); FMA2W(ai, wi.y, hreg[4 * q + 1]);
            FMA2W(ai, wi.z, hreg[4 * q + 2]); FMA2W(ai, wi.w, hreg[4 * q + 3]);
            float4 wf = shh[(32 + j) * 8 + q];
            FMA2W(af, wf.x, hreg[4 * q + 0]); FMA2W(af, wf.y, hreg[4 * q + 1]);
            FMA2W(af, wf.z, hreg[4 * q + 2]); FMA2W(af, wf.w, hreg[4 * q + 3]);
            float4 wg = shh[(64 + j) * 8 + q];
            FMA2W(ag, wg.x, hreg[4 * q + 0]); FMA2W(ag, wg.y, hreg[4 * q + 1]);
            FMA2W(ag, wg.z, hreg[4 * q + 2]); FMA2W(ag, wg.w, hreg[4 * q + 3]);
            float4 wo = shh[(96 + j) * 8 + q];
            FMA2W(ao, wo.x, hreg[4 * q + 0]); FMA2W(ao, wo.y, hreg[4 * q + 1]);
            FMA2W(ao, wo.z, hreg[4 * q + 2]); FMA2W(ao, wo.w, hreg[4 * q + 3]);
        }
        float i0, i1, f0, f1, g0, g1, o0, o1;
        unpack2(ai, i0, i1); unpack2(af, f0, f1);
        unpack2(ag, g0, g1); unpack2(ao, o0, o1);
        float cp0, cp1;
        unpack2(csh[j * 128], cp0, cp1);
        float c0 = sigm_a(f0) * cp0 + sigm_a(i0) * tanh_a(g0);
        float c1 = sigm_a(f1) * cp1 + sigm_a(i1) * tanh_a(g1);
        float h0 = sigm_a(o0) * tanh_a(c0), h1 = sigm_a(o1) * tanh_a(c1);
        float awj = sw[j];
        sacc = fma2(pack2(h0, h1), pack2(awj, awj), sacc);
    }
}

__global__ void __launch_bounds__(128, 2) k_lstm(
    const float4* __restrict__ wihf, const float4* __restrict__ whhf, const float* __restrict__ bf,
    const float4* __restrict__ wihb, const float4* __restrict__ whhb, const float* __restrict__ bb,
    const float* __restrict__ aw, const float* __restrict__ ab) {
    extern __shared__ char sm[];
    float4* sihf = (float4*)(sm + LS_SIHF);
    float4* sihb = (float4*)(sm + LS_SIHB);
    float4* shh  = (float4*)(sm + LS_SHH);
    float*  sbf  = (float*)(sm + LS_BF);
    float*  sbb  = (float*)(sm + LS_BB);
    float*  saw  = (float*)(sm + LS_AW);
    int tid = threadIdx.x;
    ull* hsh = (ull*)(sm + LS_H) + tid;
    ull* csh = (ull*)(sm + LS_C) + tid;

    for (int i = tid; i < 512; i += 128) { sihf[i] = wihf[i]; sihb[i] = wihb[i]; }
    for (int i = tid; i < 1024; i += 128) shh[i] = whhf[i];
    if (tid < 64) {
        sbf[tid] = bf[tid]; sbf[64 + tid] = bf[64 + tid];
        sbb[tid] = bb[tid]; sbb[64 + tid] = bb[64 + tid];
        saw[tid] = aw[tid];
    }
    __syncthreads();

    int n0 = blockIdx.x * 256 + tid;
    int n1 = n0 + 128;
    bool v0 = n0 < NN, v1 = n1 < NN;
    int m0 = v0 ? n0 : 0, m1 = v1 ? n1 : 0;

    ull xpa[16], xpb[16];
    {
        #pragma unroll
        for (int q = 0; q < 4; q++) {
            float4 a = g_x1[m0 * 4 + q], b = g_x1[m1 * 4 + q];
            xpa[4 * q + 0] = pack2(a.x, b.x); xpa[4 * q + 1] = pack2(a.y, b.y);
            xpa[4 * q + 2] = pack2(a.z, b.z); xpa[4 * q + 3] = pack2(a.w, b.w);
            float4 c = g_x2[m0 * 4 + q], d = g_x2[m1 * 4 + q];
            xpb[4 * q + 0] = pack2(c.x, d.x); xpb[4 * q + 1] = pack2(c.y, d.y);
            xpb[4 * q + 2] = pack2(c.z, d.z); xpb[4 * q + 3] = pack2(c.w, d.w);
        }
    }

    ull s0 = 0ULL, s1 = 0ULL;
    ull hreg[32];

    cell0p(xpa, hsh, csh, sihf, sbf, saw, s0);
    #pragma unroll
    for (int k = 0; k < 32; k++) hreg[k] = hsh[k * 128];
    cell1p(xpb, hreg, csh, sihf, shh, sbf, saw, s1);

    __syncthreads();
    for (int i = tid; i < 1024; i += 128) shh[i] = whhb[i];
    __syncthreads();

    cell0p(xpb, hsh, csh, sihb, sbb, saw + 32, s1);
    #pragma unroll
    for (int k = 0; k < 32; k++) hreg[k] = hsh[k * 128];
    cell1p(xpa, hreg, csh, sihb, shh, sbb, saw + 32, s0);

    float abv = __ldg(ab);
    float s00, s01, s10, s11;
    unpack2(s0, s00, s01); unpack2(s1, s10, s11);
    s00 += abv; s01 += abv; s10 += abv; s11 += abv;

    float mA = fmaxf(s00, s10);
    float eA0 = __expf(s00 - mA), eA1 = __expf(s10 - mA);
    float invA = __fdividef(1.0f, eA0 + eA1);
    float A0 = eA0 * invA, B0 = eA1 * invA;

    float mB = fmaxf(s01, s11);
    float eB0 = __expf(s01 - mB), eB1 = __expf(s11 - mB);
    float invB = __fdividef(1.0f, eB0 + eB1);
    float A1 = eB0 * invB, B1 = eB1 * invB;

    float fa[16], fb[16], ga[16], gb[16];
    #pragma unroll
    for (int k = 0; k < 16; k++) {
        float lo, hi;
        unpack2(xpa[k], lo, hi); fa[k] = lo; ga[k] = hi;
        unpack2(xpb[k], lo, hi); fb[k] = lo; gb[k] = hi;
    }
    if (v0) {
        #pragma unroll
        for (int q = 0; q < 4; q++) {
            g_bufA[n0 * 4 + q] = make_float4(
                A0 * fa[4 * q + 0] + B0 * fb[4 * q + 0],
                A0 * fa[4 * q + 1] + B0 * fb[4 * q + 1],
                A0 * fa[4 * q + 2] + B0 * fb[4 * q + 2],
                A0 * fa[4 * q + 3] + B0 * fb[4 * q + 3]);
        }
    }
    if (v1) {
        #pragma unroll
        for (int q = 0; q < 4; q++) {
            g_bufA[n1 * 4 + q] = make_float4(
                A1 * ga[4 * q + 0] + B1 * gb[4 * q + 0],
                A1 * ga[4 * q + 1] + B1 * gb[4 * q + 1],
                A1 * ga[4 * q + 2] + B1 * gb[4 * q + 2],
                A1 * ga[4 * q + 3] + B1 * gb[4 * q + 3]);
        }
    }
}

// ---------------- launch ----------------
extern "C" void kernel_launch(void* const* d_in, const int* in_sizes, int n_in,
                              void* d_out, int out_size) {
    int is64 = (in_sizes[1] >= 4 * NE) ? 1 : 0;

    const int NB_N  = (NN + 255) / 256;
    const int NB_E  = (NE + 255) / 256;
    const int NB_SC = (NN + 1023) / 1024;
    const int NB_W  = (NN + 7) / 8;
    const int NB_L  = (NN + 255) / 256;

    cudaFuncSetAttribute(k_lstm, cudaFuncAttributeMaxDynamicSharedMemorySize, SMEM_LSTM);
    cudaFuncSetAttribute(k_gemm1, cudaFuncAttributeMaxDynamicSharedMemorySize, SMEM_G1);

    k_zero<<<NB_N, 256>>>();
    k_count<<<NB_E, 256>>>((const int*)d_in[1], is64);
    k_scanA<<<NB_SC, 1024>>>();
    k_gemm1<<<NB_N, 256, SMEM_G1>>>((const float4*)d_in[0], (const float*)d_in[2]);
    k_scanB<<<1, 128>>>(NB_SC);
    k_scanC<<<NB_N, 256>>>();
    k_scatter<<<NB_E, 256>>>((const int*)d_in[1], is64);

    k_agg<0><<<NB_W, 256>>>(nullptr, (const float*)d_in[3], (const float4*)d_in[4], nullptr);
    k_agg<1><<<NB_W, 256>>>(nullptr, (const float*)d_in[5], nullptr, nullptr);

    k_lstm<<<NB_L, 128, SMEM_LSTM>>>(
        (const float4*)d_in[6], (const float4*)d_in[7], (const float*)d_in[8],
        (const float4*)d_in[9], (const float4*)d_in[10], (const float*)d_in[11],
        (const float*)d_in[12], (const float*)d_in[13]);

    k_agg<2><<<NB_W, 256>>>((float*)d_out, nullptr, (const float4*)d_in[14],
                            (const float*)d_in[15]);
}